// round 9
// baseline (speedup 1.0000x reference)
#include <cuda_runtime.h>
#include <cuda_bf16.h>
#include <cstddef>
#include <cstdint>

#define NMAX 100000
#define EMAX 1700000
#define D 128
#define APAD 132   // padded bf16 row stride in smem (main GEMM)
#define HPAD 264   // padded bf16 row stride (head phase, K=256)

// ---------------------------------------------------------------------------
// Scratch (device-global, allocation-free per harness rules)
// ---------------------------------------------------------------------------
__device__ float g_agg[(size_t)NMAX * D];
__device__ float g_h1[(size_t)NMAX * D];
__device__ unsigned short g_h1b[(size_t)NMAX * D];   // bf16 copy of h1
__device__ unsigned short g_xb[(size_t)NMAX * D];    // bf16 copy of x
__device__ int   g_deg[2 * NMAX];
__device__ int   g_off[2 * NMAX];
__device__ int   g_cursor[2 * NMAX];
__device__ int   g_nbr[2 * EMAX];
__device__ int   g_aux[1024];
// bf16 hi/lo layer weight images: [layer][chunk][n_outcol][k]  (transposed)
__device__ unsigned short g_wth[4 * 128 * 128];
__device__ unsigned short g_wtl[4 * 128 * 128];
// bf16 hi/lo head weight images: [n_outcol(40)][k(256)]
__device__ unsigned short g_woth[40 * 256];
__device__ unsigned short g_wotl[40 * 256];

__device__ __forceinline__ unsigned short bfu(__nv_bfloat16 b) {
    return __bfloat16_as_ushort(b);
}

// mma.sync m16n8k16 bf16 (plain-target PTX; HMMA in SASS)
__device__ __forceinline__ void mma16816(float* c, const unsigned* a, const unsigned* b) {
    asm volatile(
        "mma.sync.aligned.m16n8k16.row.col.f32.bf16.bf16.f32 "
        "{%0,%1,%2,%3}, {%4,%5,%6,%7}, {%8,%9}, {%0,%1,%2,%3};"
        : "+f"(c[0]), "+f"(c[1]), "+f"(c[2]), "+f"(c[3])
        : "r"(a[0]), "r"(a[1]), "r"(a[2]), "r"(a[3]), "r"(b[0]), "r"(b[1]));
}

__device__ __forceinline__ void split_pack(float x, float y,
                                           unsigned& hp, unsigned& lp) {
    __nv_bfloat16 hx = __float2bfloat16(x);
    __nv_bfloat16 hy = __float2bfloat16(y);
    __nv_bfloat16 lx = __float2bfloat16(x - __bfloat162float(hx));
    __nv_bfloat16 ly = __float2bfloat16(y - __bfloat162float(hy));
    hp = (unsigned)bfu(hx) | ((unsigned)bfu(hy) << 16);
    lp = (unsigned)bfu(lx) | ((unsigned)bfu(ly) << 16);
}

// ---------------------------------------------------------------------------
// prep (weights split/transpose) + zero degrees, one kernel
// ---------------------------------------------------------------------------
__global__ void __launch_bounds__(256) prep_zero_kernel(
    const float* __restrict__ wl1, const float* __restrict__ wr1,
    const float* __restrict__ wl2, const float* __restrict__ wr2,
    const float* __restrict__ w_out)
{
    int idx = blockIdx.x * 256 + threadIdx.x;   // grid = 296*256 = 75776
    for (int j = idx; j < 2 * NMAX; j += 75776) g_deg[j] = 0;
    if (idx < 65536) {
        int layer = idx >> 15;
        int rem   = idx & 32767;
        int c     = rem >> 14;
        int nrow  = (rem >> 7) & 127;
        int k     = rem & 127;
        const float* w = layer ? (c ? wr2 : wl2) : (c ? wr1 : wl1);
        float v = __ldg(w + k * 128 + nrow);
        __nv_bfloat16 hb = __float2bfloat16(v);
        __nv_bfloat16 lb = __float2bfloat16(v - __bfloat162float(hb));
        int o = (layer * 2 + c) * 16384 + nrow * 128 + k;
        g_wth[o] = bfu(hb);
        g_wtl[o] = bfu(lb);
    } else if (idx < 75776) {
        int j = idx - 65536;         // 0..10239
        int nn = j >> 8;             // 0..39
        int k  = j & 255;
        float v = __ldg(w_out + k * 40 + nn);
        __nv_bfloat16 hb = __float2bfloat16(v);
        __nv_bfloat16 lb = __float2bfloat16(v - __bfloat162float(hb));
        g_woth[nn * 256 + k] = bfu(hb);
        g_wotl[nn * 256 + k] = bfu(lb);
    }
}

// Convert x (fp32) -> g_xb (bf16)
__global__ void __launch_bounds__(256) convert_x_kernel(const float* __restrict__ x, int n) {
    int i = blockIdx.x * 256 + threadIdx.x;
    if (i >= n * 32) return;
    float4 v = __ldg(reinterpret_cast<const float4*>(x) + i);
    __nv_bfloat162 a = __floats2bfloat162_rn(v.x, v.y);
    __nv_bfloat162 b = __floats2bfloat162_rn(v.z, v.w);
    reinterpret_cast<uint2*>(g_xb)[i] =
        make_uint2(*reinterpret_cast<unsigned*>(&a), *reinterpret_cast<unsigned*>(&b));
}

// ---------------------------------------------------------------------------
// CSR build (per edge list, csr = 0/1)
// ---------------------------------------------------------------------------
__global__ void __launch_bounds__(256) count_kernel(
    const int* __restrict__ ei, int E, int csr)
{
    int e = blockIdx.x * 256 + threadIdx.x;
    if (e >= E) return;
    atomicAdd(&g_deg[csr * NMAX + __ldg(ei + E + e)], 1);
}

__global__ void __launch_bounds__(1024) scan1_kernel(int n, int a) {
    __shared__ int s[1024];
    int t = threadIdx.x;
    int i = blockIdx.x * 1024 + t;
    int v = (i < n) ? g_deg[a * NMAX + i] : 0;
    s[t] = v;
    __syncthreads();
#pragma unroll
    for (int d = 1; d < 1024; d <<= 1) {
        int add = (t >= d) ? s[t - d] : 0;
        __syncthreads();
        s[t] += add;
        __syncthreads();
    }
    if (i < n) g_off[a * NMAX + i] = s[t] - v;
    if (t == 1023) g_aux[a * 512 + blockIdx.x] = s[1023];
}

__global__ void __launch_bounds__(1024) scan2_kernel(int nb, int a) {
    __shared__ int s[1024];
    int t = threadIdx.x;
    int v = (t < nb) ? g_aux[a * 512 + t] : 0;
    s[t] = v;
    __syncthreads();
#pragma unroll
    for (int d = 1; d < 1024; d <<= 1) {
        int add = (t >= d) ? s[t - d] : 0;
        __syncthreads();
        s[t] += add;
        __syncthreads();
    }
    if (t < nb) g_aux[a * 512 + t] = s[t] - v;
}

__global__ void __launch_bounds__(256) scan3_kernel(int n, int a) {
    int i = blockIdx.x * 256 + threadIdx.x;
    if (i >= n) return;
    int o = g_off[a * NMAX + i] + g_aux[a * 512 + (i >> 10)];
    g_off[a * NMAX + i] = o;
    g_cursor[a * NMAX + i] = o;
}

__global__ void __launch_bounds__(256) fill_kernel(
    const int* __restrict__ ei, int E, int csr)
{
    int e = blockIdx.x * 256 + threadIdx.x;
    if (e >= E) return;
    int s = __ldg(ei + e);
    int d = __ldg(ei + E + e);
    int pos = atomicAdd(&g_cursor[csr * NMAX + d], 1);
    g_nbr[csr * EMAX + pos] = s;
}

// ---------------------------------------------------------------------------
// Gather-mean bf16: reads bf16 feature rows (half traffic), fp32 accumulate
// ---------------------------------------------------------------------------
__device__ __forceinline__ void add_bf16x4(float4& acc, uint2 p) {
    float2 a = __bfloat1622float2(*reinterpret_cast<__nv_bfloat162*>(&p.x));
    float2 b = __bfloat1622float2(*reinterpret_cast<__nv_bfloat162*>(&p.y));
    acc.x += a.x; acc.y += a.y; acc.z += b.x; acc.w += b.y;
}

__global__ void __launch_bounds__(256) gather_b16_kernel(
    const unsigned short* __restrict__ featb, int n, int csr)
{
    int v = (blockIdx.x * 256 + threadIdx.x) >> 5;
    int lane = threadIdx.x & 31;
    if (v >= n) return;
    int start = __ldg(g_off + csr * NMAX + v);
    int deg   = __ldg(g_deg + csr * NMAX + v);
    const int* nbr = g_nbr + csr * EMAX;
    const uint2* f = reinterpret_cast<const uint2*>(featb);
    float4 acc = make_float4(0.f, 0.f, 0.f, 0.f);
    int i = 0;
    for (; i + 4 <= deg; i += 4) {
        int s0 = __ldg(nbr + start + i);
        int s1 = __ldg(nbr + start + i + 1);
        int s2 = __ldg(nbr + start + i + 2);
        int s3 = __ldg(nbr + start + i + 3);
        uint2 p0 = __ldg(f + (size_t)s0 * 32 + lane);
        uint2 p1 = __ldg(f + (size_t)s1 * 32 + lane);
        uint2 p2 = __ldg(f + (size_t)s2 * 32 + lane);
        uint2 p3 = __ldg(f + (size_t)s3 * 32 + lane);
        add_bf16x4(acc, p0); add_bf16x4(acc, p1);
        add_bf16x4(acc, p2); add_bf16x4(acc, p3);
    }
    for (; i < deg; i++) {
        int s0 = __ldg(nbr + start + i);
        uint2 p0 = __ldg(f + (size_t)s0 * 32 + lane);
        add_bf16x4(acc, p0);
    }
    float inv = 1.0f / (float)max(deg, 1);
    acc.x *= inv; acc.y *= inv; acc.z *= inv; acc.w *= inv;
    reinterpret_cast<float4*>(g_agg)[(size_t)v * 32 + lane] = acc;
}

// ---------------------------------------------------------------------------
// HMMA SAGE layer (templated):
// MODE 0: out = g_h1 (fp32) + g_h1b (bf16 copy).  relu(agg@wl + xin@wr + b)
// MODE 1: layer-2 + fused head -> out = d_out [n,40].
// ---------------------------------------------------------------------------
template <int MODE>
__global__ void __launch_bounds__(256) layer_mma_kernel(
    const float* __restrict__ xin, const float* __restrict__ bias,
    float* __restrict__ out, int n,
    const unsigned short* __restrict__ wth_base,
    const unsigned short* __restrict__ wtl_base,
    const float* __restrict__ b_out)
{
    extern __shared__ unsigned short sm[];
    unsigned short* s_ah = sm;                       // 64 x APAD
    unsigned short* s_al = sm + 64 * APAD;
    unsigned short* s_wh = sm + 2 * 64 * APAD;       // 128 x APAD
    unsigned short* s_wl = s_wh + 128 * APAD;

    int tid = threadIdx.x, wid = tid >> 5, lane = tid & 31;
    int r0 = blockIdx.x * 64;
    int mrow = (wid & 1) * 32;
    int ncol = (wid >> 1) * 32;
    int rq = lane >> 2;

    float acc[2][4][4];
#pragma unroll
    for (int mt = 0; mt < 2; mt++)
#pragma unroll
        for (int nt = 0; nt < 4; nt++)
#pragma unroll
            for (int q = 0; q < 4; q++) acc[mt][nt][q] = 0.f;

    for (int chunk = 0; chunk < 2; chunk++) {
        if (chunk) __syncthreads();   // protect smem reuse

        // ---- stage A (64 rows), fp32 -> bf16 hi/lo split ----
        const float4* src = (chunk == 0) ? reinterpret_cast<const float4*>(g_agg)
                                         : reinterpret_cast<const float4*>(xin);
#pragma unroll
        for (int i = 0; i < 8; i++) {
            int f = tid + i * 256;          // 64 rows * 32 float4
            int row = f >> 5, k4 = f & 31;
            int gr = r0 + row;
            if (gr >= n) gr = n - 1;
            float4 v = __ldg(src + (size_t)gr * 32 + k4);
            unsigned hp0, lp0, hp1, lp1;
            split_pack(v.x, v.y, hp0, lp0);
            split_pack(v.z, v.w, hp1, lp1);
            int o = row * APAD + k4 * 4;
            *reinterpret_cast<uint2*>(s_ah + o) = make_uint2(hp0, hp1);
            *reinterpret_cast<uint2*>(s_al + o) = make_uint2(lp0, lp1);
        }

        // ---- stage W chunk (pre-split transposed images) ----
        {
            const uint2* gh = reinterpret_cast<const uint2*>(wth_base) + chunk * 4096;
            const uint2* gl = reinterpret_cast<const uint2*>(wtl_base) + chunk * 4096;
#pragma unroll
            for (int i = 0; i < 16; i++) {
                int j = tid + i * 256;        // 128 rows * 32 uint2
                int nrow = j >> 5, kk = (j & 31) * 4;
                int o = nrow * APAD + kk;
                *reinterpret_cast<uint2*>(s_wh + o) = __ldg(gh + j);
                *reinterpret_cast<uint2*>(s_wl + o) = __ldg(gl + j);
            }
        }
        __syncthreads();

        // ---- compute: 8 k-steps of m16n8k16, 3 products ----
#pragma unroll
        for (int s = 0; s < 8; s++) {
            int kc = s * 16 + (lane & 3) * 2;
            unsigned bh[4][2], bl[4][2];
#pragma unroll
            for (int nt = 0; nt < 4; nt++) {
                int nn = ncol + nt * 8 + rq;
                bh[nt][0] = *reinterpret_cast<unsigned*>(s_wh + nn * APAD + kc);
                bh[nt][1] = *reinterpret_cast<unsigned*>(s_wh + nn * APAD + kc + 8);
                bl[nt][0] = *reinterpret_cast<unsigned*>(s_wl + nn * APAD + kc);
                bl[nt][1] = *reinterpret_cast<unsigned*>(s_wl + nn * APAD + kc + 8);
            }
#pragma unroll
            for (int mt = 0; mt < 2; mt++) {
                int rr = mrow + mt * 16 + rq;
                unsigned ah[4], al[4];
                ah[0] = *reinterpret_cast<unsigned*>(s_ah + rr * APAD + kc);
                ah[1] = *reinterpret_cast<unsigned*>(s_ah + (rr + 8) * APAD + kc);
                ah[2] = *reinterpret_cast<unsigned*>(s_ah + rr * APAD + kc + 8);
                ah[3] = *reinterpret_cast<unsigned*>(s_ah + (rr + 8) * APAD + kc + 8);
                al[0] = *reinterpret_cast<unsigned*>(s_al + rr * APAD + kc);
                al[1] = *reinterpret_cast<unsigned*>(s_al + (rr + 8) * APAD + kc);
                al[2] = *reinterpret_cast<unsigned*>(s_al + rr * APAD + kc + 8);
                al[3] = *reinterpret_cast<unsigned*>(s_al + (rr + 8) * APAD + kc + 8);
#pragma unroll
                for (int nt = 0; nt < 4; nt++) {
                    mma16816(acc[mt][nt], ah, bh[nt]);   // hi*hi
                    mma16816(acc[mt][nt], ah, bl[nt]);   // hi*lo
                    mma16816(acc[mt][nt], al, bh[nt]);   // lo*hi
                }
            }
        }
    }

    if (MODE == 0) {
        // ---- epilogue: bias + relu -> g_h1 (fp32) + g_h1b (bf16) ----
#pragma unroll
        for (int mt = 0; mt < 2; mt++) {
#pragma unroll
            for (int nt = 0; nt < 4; nt++) {
                int col = ncol + nt * 8 + (lane & 3) * 2;
                float bx = __ldg(bias + col), by = __ldg(bias + col + 1);
#pragma unroll
                for (int q2 = 0; q2 < 2; q2++) {
                    int row = r0 + mrow + mt * 16 + rq + q2 * 8;
                    if (row < n) {
                        float vx = fmaxf(acc[mt][nt][q2 * 2 + 0] + bx, 0.f);
                        float vy = fmaxf(acc[mt][nt][q2 * 2 + 1] + by, 0.f);
                        *reinterpret_cast<float2*>(out + (size_t)row * 128 + col)
                            = make_float2(vx, vy);
                        __nv_bfloat162 bb = __floats2bfloat162_rn(vx, vy);
                        *reinterpret_cast<unsigned*>(g_h1b + (size_t)row * 128 + col)
                            = *reinterpret_cast<unsigned*>(&bb);
                    }
                }
            }
        }
        return;
    }

    // ================= MODE 1: fused head =================
    __syncthreads();   // everyone done reading main-phase smem

    unsigned short* s_hh = sm;
    unsigned short* s_hl = sm + 64 * HPAD;
    unsigned short* s_oh = sm + 2 * 64 * HPAD;
    unsigned short* s_ol = s_oh + 40 * HPAD;

    // 1) store relu(h2)+bias fragments into cat-tile cols [128..256)
#pragma unroll
    for (int mt = 0; mt < 2; mt++) {
#pragma unroll
        for (int nt = 0; nt < 4; nt++) {
            int col = ncol + nt * 8 + (lane & 3) * 2;
            float bx = __ldg(bias + col), by = __ldg(bias + col + 1);
#pragma unroll
            for (int q2 = 0; q2 < 2; q2++) {
                int row = mrow + mt * 16 + rq + q2 * 8;
                float vx = fmaxf(acc[mt][nt][q2 * 2 + 0] + bx, 0.f);
                float vy = fmaxf(acc[mt][nt][q2 * 2 + 1] + by, 0.f);
                unsigned hp, lp;
                split_pack(vx, vy, hp, lp);
                int o = row * HPAD + 128 + col;
                *reinterpret_cast<unsigned*>(s_hh + o) = hp;
                *reinterpret_cast<unsigned*>(s_hl + o) = lp;
            }
        }
    }

    // 2) load h1 rows (fp32) into cat-tile cols [0..128)
    {
        const float4* h14 = reinterpret_cast<const float4*>(xin);  // xin == g_h1
#pragma unroll
        for (int i = 0; i < 8; i++) {
            int f = tid + i * 256;
            int row = f >> 5, k4 = f & 31;
            int gr = r0 + row;
            if (gr >= n) gr = n - 1;
            float4 v = __ldg(h14 + (size_t)gr * 32 + k4);
            unsigned hp0, lp0, hp1, lp1;
            split_pack(v.x, v.y, hp0, lp0);
            split_pack(v.z, v.w, hp1, lp1);
            int o = row * HPAD + k4 * 4;
            *reinterpret_cast<uint2*>(s_hh + o) = make_uint2(hp0, hp1);
            *reinterpret_cast<uint2*>(s_hl + o) = make_uint2(lp0, lp1);
        }
    }

    // 3) stage w_out images [40 x 256] hi/lo
    {
        const uint2* gh = reinterpret_cast<const uint2*>(g_woth);
        const uint2* gl = reinterpret_cast<const uint2*>(g_wotl);
#pragma unroll
        for (int i = 0; i < 10; i++) {
            int j = tid + i * 256;            // 40*64 = 2560
            if (j < 2560) {
                int nn = j >> 6, kk = (j & 63) * 4;
                int o = nn * HPAD + kk;
                *reinterpret_cast<uint2*>(s_oh + o) = __ldg(gh + j);
                *reinterpret_cast<uint2*>(s_ol + o) = __ldg(gl + j);
            }
        }
    }
    __syncthreads();

    // 4) head GEMM
    int wg = wid >> 1;
    int mrow2 = (wid & 1) * 32;
    int nts0 = wg, nts1 = 4;
    int nnt = (wg == 0) ? 2 : 1;

    float acc2[2][2][4];
#pragma unroll
    for (int mt = 0; mt < 2; mt++)
#pragma unroll
        for (int t = 0; t < 2; t++)
#pragma unroll
            for (int q = 0; q < 4; q++) acc2[mt][t][q] = 0.f;

#pragma unroll
    for (int s = 0; s < 16; s++) {
        int kc = s * 16 + (lane & 3) * 2;
        unsigned bh[2][2], bl[2][2];
        for (int t = 0; t < nnt; t++) {
            int nt = t ? nts1 : nts0;
            int nn = nt * 8 + rq;
            bh[t][0] = *reinterpret_cast<unsigned*>(s_oh + nn * HPAD + kc);
            bh[t][1] = *reinterpret_cast<unsigned*>(s_oh + nn * HPAD + kc + 8);
            bl[t][0] = *reinterpret_cast<unsigned*>(s_ol + nn * HPAD + kc);
            bl[t][1] = *reinterpret_cast<unsigned*>(s_ol + nn * HPAD + kc + 8);
        }
#pragma unroll
        for (int mt = 0; mt < 2; mt++) {
            int rr = mrow2 + mt * 16 + rq;
            unsigned ah[4], al[4];
            ah[0] = *reinterpret_cast<unsigned*>(s_hh + rr * HPAD + kc);
            ah[1] = *reinterpret_cast<unsigned*>(s_hh + (rr + 8) * HPAD + kc);
            ah[2] = *reinterpret_cast<unsigned*>(s_hh + rr * HPAD + kc + 8);
            ah[3] = *reinterpret_cast<unsigned*>(s_hh + (rr + 8) * HPAD + kc + 8);
            al[0] = *reinterpret_cast<unsigned*>(s_hl + rr * HPAD + kc);
            al[1] = *reinterpret_cast<unsigned*>(s_hl + (rr + 8) * HPAD + kc);
            al[2] = *reinterpret_cast<unsigned*>(s_hl + rr * HPAD + kc + 8);
            al[3] = *reinterpret_cast<unsigned*>(s_hl + (rr + 8) * HPAD + kc + 8);
            for (int t = 0; t < nnt; t++) {
                mma16816(acc2[mt][t], ah, bh[t]);
                mma16816(acc2[mt][t], ah, bl[t]);
                mma16816(acc2[mt][t], al, bh[t]);
            }
        }
    }

    // 5) write d_out
#pragma unroll
    for (int mt = 0; mt < 2; mt++) {
        for (int t = 0; t < nnt; t++) {
            int nt = t ? nts1 : nts0;
            int col = nt * 8 + (lane & 3) * 2;
            float bx = __ldg(b_out + col), by = __ldg(b_out + col + 1);
#pragma unroll
            for (int q2 = 0; q2 < 2; q2++) {
                int row = r0 + mrow2 + mt * 16 + rq + q2 * 8;
                if (row < n) {
                    float2 o = make_float2(acc2[mt][t][q2 * 2 + 0] + bx,
                                           acc2[mt][t][q2 * 2 + 1] + by);
                    *reinterpret_cast<float2*>(out + (size_t)row * 40 + col) = o;
                }
            }
        }
    }
}

// ---------------------------------------------------------------------------
extern "C" void kernel_launch(void* const* d_in, const int* in_sizes, int n_in,
                              void* d_out, int out_size)
{
    const float* x     = (const float*)d_in[0];
    const int*   ei1   = (const int*)d_in[1];
    const int*   ei2   = (const int*)d_in[2];
    const float* wl1   = (const float*)d_in[3];
    const float* wr1   = (const float*)d_in[4];
    const float* b1    = (const float*)d_in[5];
    const float* wl2   = (const float*)d_in[6];
    const float* wr2   = (const float*)d_in[7];
    const float* b2    = (const float*)d_in[8];
    const float* w_out = (const float*)d_in[9];
    const float* b_out = (const float*)d_in[10];

    int n  = in_sizes[0] / D;
    int E1 = in_sizes[1] / 2;
    int E2 = in_sizes[2] / 2;

    void *p_h1 = nullptr, *p_wth = nullptr, *p_wtl = nullptr;
    void *p_xb = nullptr, *p_h1b = nullptr;
    cudaGetSymbolAddress(&p_h1, g_h1);
    cudaGetSymbolAddress(&p_wth, g_wth);
    cudaGetSymbolAddress(&p_wtl, g_wtl);
    cudaGetSymbolAddress(&p_xb, g_xb);
    cudaGetSymbolAddress(&p_h1b, g_h1b);
    float* h1 = (float*)p_h1;
    const unsigned short* wth = (const unsigned short*)p_wth;
    const unsigned short* wtl = (const unsigned short*)p_wtl;
    const unsigned short* xb  = (const unsigned short*)p_xb;
    const unsigned short* h1b = (const unsigned short*)p_h1b;

    const int LAYER_SMEM = 2 * 64 * HPAD * 2 + 2 * 40 * HPAD * 2;  // 109824 B
    cudaFuncSetAttribute(layer_mma_kernel<0>,
                         cudaFuncAttributeMaxDynamicSharedMemorySize, LAYER_SMEM);
    cudaFuncSetAttribute(layer_mma_kernel<1>,
                         cudaFuncAttributeMaxDynamicSharedMemorySize, LAYER_SMEM);

    int nb_scan = (n + 1023) / 1024;
    int layer_blocks = (n + 63) / 64;
    int gather_blocks = (n * 32 + 255) / 256;

    // Side stream for CSR-2 build (event fork/join; capture-safe pattern).
    cudaStream_t sB;
    cudaEvent_t eFork, eJoin;
    cudaStreamCreateWithFlags(&sB, cudaStreamNonBlocking);
    cudaEventCreateWithFlags(&eFork, cudaEventDisableTiming);
    cudaEventCreateWithFlags(&eJoin, cudaEventDisableTiming);

    // ---- prep (zero degs + weight images) on main stream ----
    prep_zero_kernel<<<296, 256>>>(wl1, wr1, wl2, wr2, w_out);

    // fork: CSR-2 build on sB (depends only on zeroed degrees)
    cudaEventRecord(eFork, 0);
    cudaStreamWaitEvent(sB, eFork, 0);
    count_kernel<<<(E2 + 255) / 256, 256, 0, sB>>>(ei2, E2, 1);
    scan1_kernel<<<nb_scan, 1024, 0, sB>>>(n, 1);
    scan2_kernel<<<1, 1024, 0, sB>>>(nb_scan, 1);
    scan3_kernel<<<(n + 255) / 256, 256, 0, sB>>>(n, 1);
    fill_kernel<<<(E2 + 255) / 256, 256, 0, sB>>>(ei2, E2, 1);
    cudaEventRecord(eJoin, sB);

    // ---- main stream: convert x, CSR-1, gather1, layer1 ----
    convert_x_kernel<<<(n * 32 + 255) / 256, 256>>>(x, n);
    count_kernel<<<(E1 + 255) / 256, 256>>>(ei1, E1, 0);
    scan1_kernel<<<nb_scan, 1024>>>(n, 0);
    scan2_kernel<<<1, 1024>>>(nb_scan, 0);
    scan3_kernel<<<(n + 255) / 256, 256>>>(n, 0);
    fill_kernel<<<(E1 + 255) / 256, 256>>>(ei1, E1, 0);

    gather_b16_kernel<<<gather_blocks, 256>>>(xb, n, 0);
    layer_mma_kernel<0><<<layer_blocks, 256, LAYER_SMEM>>>(
        x, b1, h1, n, wth, wtl, b_out);

    // join CSR-2, then layer 2 + fused head
    cudaStreamWaitEvent(0, eJoin, 0);
    gather_b16_kernel<<<gather_blocks, 256>>>(h1b, n, 1);
    layer_mma_kernel<1><<<layer_blocks, 256, LAYER_SMEM>>>(
        h1, b2, (float*)d_out, n, wth + 32768, wtl + 32768, b_out);
}

// round 10
// speedup vs baseline: 1.0102x; 1.0102x over previous
#include <cuda_runtime.h>
#include <cuda_bf16.h>
#include <cstddef>
#include <cstdint>

#define NMAX 100000
#define EMAX 1700000
#define D 128
#define APAD 132   // padded bf16 row stride in smem (main GEMM)
#define HPAD 264   // padded bf16 row stride (head phase, K=256)

// ---------------------------------------------------------------------------
// Scratch (device-global, allocation-free per harness rules)
// ---------------------------------------------------------------------------
__device__ float g_agg[(size_t)NMAX * D];
__device__ float g_h1[(size_t)NMAX * D];
__device__ unsigned short g_h1b[(size_t)NMAX * D];   // bf16 copy of h1
__device__ unsigned short g_xb[(size_t)NMAX * D];    // bf16 copy of x
__device__ int   g_deg[2 * NMAX];
__device__ int   g_off[2 * NMAX];
__device__ int   g_cursor[2 * NMAX];
__device__ int   g_nbr[2 * EMAX];
__device__ int   g_aux[1024];
// bf16 hi/lo layer weight images: [layer][chunk][n_outcol][k]  (transposed)
__device__ unsigned short g_wth[4 * 128 * 128];
__device__ unsigned short g_wtl[4 * 128 * 128];
// bf16 hi/lo head weight images: [n_outcol(40)][k(256)]
__device__ unsigned short g_woth[40 * 256];
__device__ unsigned short g_wotl[40 * 256];

__device__ __forceinline__ unsigned short bfu(__nv_bfloat16 b) {
    return __bfloat16_as_ushort(b);
}

// mma.sync m16n8k16 bf16 (plain-target PTX; HMMA in SASS)
__device__ __forceinline__ void mma16816(float* c, const unsigned* a, const unsigned* b) {
    asm volatile(
        "mma.sync.aligned.m16n8k16.row.col.f32.bf16.bf16.f32 "
        "{%0,%1,%2,%3}, {%4,%5,%6,%7}, {%8,%9}, {%0,%1,%2,%3};"
        : "+f"(c[0]), "+f"(c[1]), "+f"(c[2]), "+f"(c[3])
        : "r"(a[0]), "r"(a[1]), "r"(a[2]), "r"(a[3]), "r"(b[0]), "r"(b[1]));
}

__device__ __forceinline__ void split_pack(float x, float y,
                                           unsigned& hp, unsigned& lp) {
    __nv_bfloat16 hx = __float2bfloat16(x);
    __nv_bfloat16 hy = __float2bfloat16(y);
    __nv_bfloat16 lx = __float2bfloat16(x - __bfloat162float(hx));
    __nv_bfloat16 ly = __float2bfloat16(y - __bfloat162float(hy));
    hp = (unsigned)bfu(hx) | ((unsigned)bfu(hy) << 16);
    lp = (unsigned)bfu(lx) | ((unsigned)bfu(ly) << 16);
}

// ---------------------------------------------------------------------------
// prep: weight split/transpose + zero degrees + convert x -> bf16, one kernel
// grid = 2048 x 256
// ---------------------------------------------------------------------------
__global__ void __launch_bounds__(256) prep_kernel(
    const float* __restrict__ wl1, const float* __restrict__ wr1,
    const float* __restrict__ wl2, const float* __restrict__ wr2,
    const float* __restrict__ w_out, const float* __restrict__ x, int n)
{
    int idx = blockIdx.x * 256 + threadIdx.x;
    const int NT = 2048 * 256;
    // zero degrees
    for (int j = idx; j < 2 * NMAX; j += NT) g_deg[j] = 0;
    // convert x -> bf16 (n*32 float4 groups)
    for (int i = idx; i < n * 32; i += NT) {
        float4 v = __ldg(reinterpret_cast<const float4*>(x) + i);
        __nv_bfloat162 a = __floats2bfloat162_rn(v.x, v.y);
        __nv_bfloat162 b = __floats2bfloat162_rn(v.z, v.w);
        reinterpret_cast<uint2*>(g_xb)[i] =
            make_uint2(*reinterpret_cast<unsigned*>(&a), *reinterpret_cast<unsigned*>(&b));
    }
    // weight images
    if (idx < 65536) {
        int layer = idx >> 15;
        int rem   = idx & 32767;
        int c     = rem >> 14;
        int nrow  = (rem >> 7) & 127;
        int k     = rem & 127;
        const float* w = layer ? (c ? wr2 : wl2) : (c ? wr1 : wl1);
        float v = __ldg(w + k * 128 + nrow);
        __nv_bfloat16 hb = __float2bfloat16(v);
        __nv_bfloat16 lb = __float2bfloat16(v - __bfloat162float(hb));
        int o = (layer * 2 + c) * 16384 + nrow * 128 + k;
        g_wth[o] = bfu(hb);
        g_wtl[o] = bfu(lb);
    } else if (idx < 75776) {
        int j = idx - 65536;
        int nn = j >> 8;
        int k  = j & 255;
        float v = __ldg(w_out + k * 40 + nn);
        __nv_bfloat16 hb = __float2bfloat16(v);
        __nv_bfloat16 lb = __float2bfloat16(v - __bfloat162float(hb));
        g_woth[nn * 256 + k] = bfu(hb);
        g_wotl[nn * 256 + k] = bfu(lb);
    }
}

// ---------------------------------------------------------------------------
// Merged CSR build for both edge lists
// ---------------------------------------------------------------------------
__global__ void __launch_bounds__(256) count_both_kernel(
    const int* __restrict__ ei1, const int* __restrict__ ei2, int E1, int E2)
{
    int e = blockIdx.x * 256 + threadIdx.x;
    if (e < E1) atomicAdd(&g_deg[__ldg(ei1 + E1 + e)], 1);
    int e2 = e - E1;
    if (e2 >= 0 && e2 < E2) atomicAdd(&g_deg[NMAX + __ldg(ei2 + E2 + e2)], 1);
}

__global__ void __launch_bounds__(1024) scan1_kernel(int n) {
    __shared__ int s[1024];
    int a = blockIdx.y;
    int t = threadIdx.x;
    int i = blockIdx.x * 1024 + t;
    int v = (i < n) ? g_deg[a * NMAX + i] : 0;
    s[t] = v;
    __syncthreads();
#pragma unroll
    for (int d = 1; d < 1024; d <<= 1) {
        int add = (t >= d) ? s[t - d] : 0;
        __syncthreads();
        s[t] += add;
        __syncthreads();
    }
    if (i < n) g_off[a * NMAX + i] = s[t] - v;   // exclusive within chunk
    if (t == 1023) g_aux[a * 512 + blockIdx.x] = s[1023];   // chunk total
}

// fused scan2+scan3: each block computes its chunk's prefix locally
__global__ void __launch_bounds__(256) scan23_kernel(int n, int nb) {
    __shared__ int s[128];
    int a = blockIdx.y;
    int i = blockIdx.x * 256 + threadIdx.x;
    int c = blockIdx.x >> 2;          // 1024-elem chunk index (4 blocks/chunk)
    if (threadIdx.x < nb) s[threadIdx.x] = g_aux[a * 512 + threadIdx.x];
    __syncthreads();
    int pre = 0;
    for (int j = 0; j < c; j++) pre += s[j];   // uniform short loop
    if (i < n) {
        int o = g_off[a * NMAX + i] + pre;
        g_off[a * NMAX + i] = o;
        g_cursor[a * NMAX + i] = o;
    }
}

__global__ void __launch_bounds__(256) fill_both_kernel(
    const int* __restrict__ ei1, const int* __restrict__ ei2, int E1, int E2)
{
    int e = blockIdx.x * 256 + threadIdx.x;
    if (e < E1) {
        int s = __ldg(ei1 + e);
        int d = __ldg(ei1 + E1 + e);
        int pos = atomicAdd(&g_cursor[d], 1);
        g_nbr[pos] = s;
    }
    int e2 = e - E1;
    if (e2 >= 0 && e2 < E2) {
        int s = __ldg(ei2 + e2);
        int d = __ldg(ei2 + E2 + e2);
        int pos = atomicAdd(&g_cursor[NMAX + d], 1);
        g_nbr[EMAX + pos] = s;
    }
}

// ---------------------------------------------------------------------------
// Gather-mean bf16: reads bf16 feature rows (half traffic), fp32 accumulate
// ---------------------------------------------------------------------------
__device__ __forceinline__ void add_bf16x4(float4& acc, uint2 p) {
    float2 a = __bfloat1622float2(*reinterpret_cast<__nv_bfloat162*>(&p.x));
    float2 b = __bfloat1622float2(*reinterpret_cast<__nv_bfloat162*>(&p.y));
    acc.x += a.x; acc.y += a.y; acc.z += b.x; acc.w += b.y;
}

__global__ void __launch_bounds__(256) gather_b16_kernel(
    const unsigned short* __restrict__ featb, int n, int csr)
{
    int v = (blockIdx.x * 256 + threadIdx.x) >> 5;
    int lane = threadIdx.x & 31;
    if (v >= n) return;
    int start = __ldg(g_off + csr * NMAX + v);
    int deg   = __ldg(g_deg + csr * NMAX + v);
    const int* nbr = g_nbr + csr * EMAX;
    const uint2* f = reinterpret_cast<const uint2*>(featb);
    float4 acc = make_float4(0.f, 0.f, 0.f, 0.f);
    int i = 0;
    for (; i + 4 <= deg; i += 4) {
        int s0 = __ldg(nbr + start + i);
        int s1 = __ldg(nbr + start + i + 1);
        int s2 = __ldg(nbr + start + i + 2);
        int s3 = __ldg(nbr + start + i + 3);
        uint2 p0 = __ldg(f + (size_t)s0 * 32 + lane);
        uint2 p1 = __ldg(f + (size_t)s1 * 32 + lane);
        uint2 p2 = __ldg(f + (size_t)s2 * 32 + lane);
        uint2 p3 = __ldg(f + (size_t)s3 * 32 + lane);
        add_bf16x4(acc, p0); add_bf16x4(acc, p1);
        add_bf16x4(acc, p2); add_bf16x4(acc, p3);
    }
    for (; i < deg; i++) {
        int s0 = __ldg(nbr + start + i);
        uint2 p0 = __ldg(f + (size_t)s0 * 32 + lane);
        add_bf16x4(acc, p0);
    }
    float inv = 1.0f / (float)max(deg, 1);
    acc.x *= inv; acc.y *= inv; acc.z *= inv; acc.w *= inv;
    reinterpret_cast<float4*>(g_agg)[(size_t)v * 32 + lane] = acc;
}

// ---------------------------------------------------------------------------
// HMMA SAGE layer (templated):
// MODE 0: out = g_h1 (fp32) + g_h1b (bf16 copy).  relu(agg@wl + xin@wr + b)
// MODE 1: layer-2 + fused head -> out = d_out [n,40].
// ---------------------------------------------------------------------------
template <int MODE>
__global__ void __launch_bounds__(256) layer_mma_kernel(
    const float* __restrict__ xin, const float* __restrict__ bias,
    float* __restrict__ out, int n,
    const unsigned short* __restrict__ wth_base,
    const unsigned short* __restrict__ wtl_base,
    const float* __restrict__ b_out)
{
    extern __shared__ unsigned short sm[];
    unsigned short* s_ah = sm;                       // 64 x APAD
    unsigned short* s_al = sm + 64 * APAD;
    unsigned short* s_wh = sm + 2 * 64 * APAD;       // 128 x APAD
    unsigned short* s_wl = s_wh + 128 * APAD;

    int tid = threadIdx.x, wid = tid >> 5, lane = tid & 31;
    int r0 = blockIdx.x * 64;
    int mrow = (wid & 1) * 32;
    int ncol = (wid >> 1) * 32;
    int rq = lane >> 2;

    float acc[2][4][4];
#pragma unroll
    for (int mt = 0; mt < 2; mt++)
#pragma unroll
        for (int nt = 0; nt < 4; nt++)
#pragma unroll
            for (int q = 0; q < 4; q++) acc[mt][nt][q] = 0.f;

    for (int chunk = 0; chunk < 2; chunk++) {
        if (chunk) __syncthreads();   // protect smem reuse

        // ---- stage A (64 rows), fp32 -> bf16 hi/lo split ----
        const float4* src = (chunk == 0) ? reinterpret_cast<const float4*>(g_agg)
                                         : reinterpret_cast<const float4*>(xin);
#pragma unroll
        for (int i = 0; i < 8; i++) {
            int f = tid + i * 256;          // 64 rows * 32 float4
            int row = f >> 5, k4 = f & 31;
            int gr = r0 + row;
            if (gr >= n) gr = n - 1;
            float4 v = __ldg(src + (size_t)gr * 32 + k4);
            unsigned hp0, lp0, hp1, lp1;
            split_pack(v.x, v.y, hp0, lp0);
            split_pack(v.z, v.w, hp1, lp1);
            int o = row * APAD + k4 * 4;
            *reinterpret_cast<uint2*>(s_ah + o) = make_uint2(hp0, hp1);
            *reinterpret_cast<uint2*>(s_al + o) = make_uint2(lp0, lp1);
        }

        // ---- stage W chunk (pre-split transposed images) ----
        {
            const uint2* gh = reinterpret_cast<const uint2*>(wth_base) + chunk * 4096;
            const uint2* gl = reinterpret_cast<const uint2*>(wtl_base) + chunk * 4096;
#pragma unroll
            for (int i = 0; i < 16; i++) {
                int j = tid + i * 256;        // 128 rows * 32 uint2
                int nrow = j >> 5, kk = (j & 31) * 4;
                int o = nrow * APAD + kk;
                *reinterpret_cast<uint2*>(s_wh + o) = __ldg(gh + j);
                *reinterpret_cast<uint2*>(s_wl + o) = __ldg(gl + j);
            }
        }
        __syncthreads();

        // ---- compute: 8 k-steps of m16n8k16, 3 products ----
#pragma unroll
        for (int s = 0; s < 8; s++) {
            int kc = s * 16 + (lane & 3) * 2;
            unsigned bh[4][2], bl[4][2];
#pragma unroll
            for (int nt = 0; nt < 4; nt++) {
                int nn = ncol + nt * 8 + rq;
                bh[nt][0] = *reinterpret_cast<unsigned*>(s_wh + nn * APAD + kc);
                bh[nt][1] = *reinterpret_cast<unsigned*>(s_wh + nn * APAD + kc + 8);
                bl[nt][0] = *reinterpret_cast<unsigned*>(s_wl + nn * APAD + kc);
                bl[nt][1] = *reinterpret_cast<unsigned*>(s_wl + nn * APAD + kc + 8);
            }
#pragma unroll
            for (int mt = 0; mt < 2; mt++) {
                int rr = mrow + mt * 16 + rq;
                unsigned ah[4], al[4];
                ah[0] = *reinterpret_cast<unsigned*>(s_ah + rr * APAD + kc);
                ah[1] = *reinterpret_cast<unsigned*>(s_ah + (rr + 8) * APAD + kc);
                ah[2] = *reinterpret_cast<unsigned*>(s_ah + rr * APAD + kc + 8);
                ah[3] = *reinterpret_cast<unsigned*>(s_ah + (rr + 8) * APAD + kc + 8);
                al[0] = *reinterpret_cast<unsigned*>(s_al + rr * APAD + kc);
                al[1] = *reinterpret_cast<unsigned*>(s_al + (rr + 8) * APAD + kc);
                al[2] = *reinterpret_cast<unsigned*>(s_al + rr * APAD + kc + 8);
                al[3] = *reinterpret_cast<unsigned*>(s_al + (rr + 8) * APAD + kc + 8);
#pragma unroll
                for (int nt = 0; nt < 4; nt++) {
                    mma16816(acc[mt][nt], ah, bh[nt]);   // hi*hi
                    mma16816(acc[mt][nt], ah, bl[nt]);   // hi*lo
                    mma16816(acc[mt][nt], al, bh[nt]);   // lo*hi
                }
            }
        }
    }

    if (MODE == 0) {
        // ---- epilogue: bias + relu -> g_h1 (fp32) + g_h1b (bf16) ----
#pragma unroll
        for (int mt = 0; mt < 2; mt++) {
#pragma unroll
            for (int nt = 0; nt < 4; nt++) {
                int col = ncol + nt * 8 + (lane & 3) * 2;
                float bx = __ldg(bias + col), by = __ldg(bias + col + 1);
#pragma unroll
                for (int q2 = 0; q2 < 2; q2++) {
                    int row = r0 + mrow + mt * 16 + rq + q2 * 8;
                    if (row < n) {
                        float vx = fmaxf(acc[mt][nt][q2 * 2 + 0] + bx, 0.f);
                        float vy = fmaxf(acc[mt][nt][q2 * 2 + 1] + by, 0.f);
                        *reinterpret_cast<float2*>(out + (size_t)row * 128 + col)
                            = make_float2(vx, vy);
                        __nv_bfloat162 bb = __floats2bfloat162_rn(vx, vy);
                        *reinterpret_cast<unsigned*>(g_h1b + (size_t)row * 128 + col)
                            = *reinterpret_cast<unsigned*>(&bb);
                    }
                }
            }
        }
        return;
    }

    // ================= MODE 1: fused head =================
    __syncthreads();   // everyone done reading main-phase smem

    unsigned short* s_hh = sm;
    unsigned short* s_hl = sm + 64 * HPAD;
    unsigned short* s_oh = sm + 2 * 64 * HPAD;
    unsigned short* s_ol = s_oh + 40 * HPAD;

    // 1) store relu(h2)+bias fragments into cat-tile cols [128..256)
#pragma unroll
    for (int mt = 0; mt < 2; mt++) {
#pragma unroll
        for (int nt = 0; nt < 4; nt++) {
            int col = ncol + nt * 8 + (lane & 3) * 2;
            float bx = __ldg(bias + col), by = __ldg(bias + col + 1);
#pragma unroll
            for (int q2 = 0; q2 < 2; q2++) {
                int row = mrow + mt * 16 + rq + q2 * 8;
                float vx = fmaxf(acc[mt][nt][q2 * 2 + 0] + bx, 0.f);
                float vy = fmaxf(acc[mt][nt][q2 * 2 + 1] + by, 0.f);
                unsigned hp, lp;
                split_pack(vx, vy, hp, lp);
                int o = row * HPAD + 128 + col;
                *reinterpret_cast<unsigned*>(s_hh + o) = hp;
                *reinterpret_cast<unsigned*>(s_hl + o) = lp;
            }
        }
    }

    // 2) load h1 rows (fp32) into cat-tile cols [0..128)
    {
        const float4* h14 = reinterpret_cast<const float4*>(xin);  // xin == g_h1
#pragma unroll
        for (int i = 0; i < 8; i++) {
            int f = tid + i * 256;
            int row = f >> 5, k4 = f & 31;
            int gr = r0 + row;
            if (gr >= n) gr = n - 1;
            float4 v = __ldg(h14 + (size_t)gr * 32 + k4);
            unsigned hp0, lp0, hp1, lp1;
            split_pack(v.x, v.y, hp0, lp0);
            split_pack(v.z, v.w, hp1, lp1);
            int o = row * HPAD + k4 * 4;
            *reinterpret_cast<uint2*>(s_hh + o) = make_uint2(hp0, hp1);
            *reinterpret_cast<uint2*>(s_hl + o) = make_uint2(lp0, lp1);
        }
    }

    // 3) stage w_out images [40 x 256] hi/lo
    {
        const uint2* gh = reinterpret_cast<const uint2*>(g_woth);
        const uint2* gl = reinterpret_cast<const uint2*>(g_wotl);
#pragma unroll
        for (int i = 0; i < 10; i++) {
            int j = tid + i * 256;            // 40*64 = 2560
            if (j < 2560) {
                int nn = j >> 6, kk = (j & 63) * 4;
                int o = nn * HPAD + kk;
                *reinterpret_cast<uint2*>(s_oh + o) = __ldg(gh + j);
                *reinterpret_cast<uint2*>(s_ol + o) = __ldg(gl + j);
            }
        }
    }
    __syncthreads();

    // 4) head GEMM
    int wg = wid >> 1;
    int mrow2 = (wid & 1) * 32;
    int nts0 = wg, nts1 = 4;
    int nnt = (wg == 0) ? 2 : 1;

    float acc2[2][2][4];
#pragma unroll
    for (int mt = 0; mt < 2; mt++)
#pragma unroll
        for (int t = 0; t < 2; t++)
#pragma unroll
            for (int q = 0; q < 4; q++) acc2[mt][t][q] = 0.f;

#pragma unroll
    for (int s = 0; s < 16; s++) {
        int kc = s * 16 + (lane & 3) * 2;
        unsigned bh[2][2], bl[2][2];
        for (int t = 0; t < nnt; t++) {
            int nt = t ? nts1 : nts0;
            int nn = nt * 8 + rq;
            bh[t][0] = *reinterpret_cast<unsigned*>(s_oh + nn * HPAD + kc);
            bh[t][1] = *reinterpret_cast<unsigned*>(s_oh + nn * HPAD + kc + 8);
            bl[t][0] = *reinterpret_cast<unsigned*>(s_ol + nn * HPAD + kc);
            bl[t][1] = *reinterpret_cast<unsigned*>(s_ol + nn * HPAD + kc + 8);
        }
#pragma unroll
        for (int mt = 0; mt < 2; mt++) {
            int rr = mrow2 + mt * 16 + rq;
            unsigned ah[4], al[4];
            ah[0] = *reinterpret_cast<unsigned*>(s_hh + rr * HPAD + kc);
            ah[1] = *reinterpret_cast<unsigned*>(s_hh + (rr + 8) * HPAD + kc);
            ah[2] = *reinterpret_cast<unsigned*>(s_hh + rr * HPAD + kc + 8);
            ah[3] = *reinterpret_cast<unsigned*>(s_hh + (rr + 8) * HPAD + kc + 8);
            al[0] = *reinterpret_cast<unsigned*>(s_hl + rr * HPAD + kc);
            al[1] = *reinterpret_cast<unsigned*>(s_hl + (rr + 8) * HPAD + kc);
            al[2] = *reinterpret_cast<unsigned*>(s_hl + rr * HPAD + kc + 8);
            al[3] = *reinterpret_cast<unsigned*>(s_hl + (rr + 8) * HPAD + kc + 8);
            for (int t = 0; t < nnt; t++) {
                mma16816(acc2[mt][t], ah, bh[t]);
                mma16816(acc2[mt][t], ah, bl[t]);
                mma16816(acc2[mt][t], al, bh[t]);
            }
        }
    }

    // 5) write d_out
#pragma unroll
    for (int mt = 0; mt < 2; mt++) {
        for (int t = 0; t < nnt; t++) {
            int nt = t ? nts1 : nts0;
            int col = nt * 8 + (lane & 3) * 2;
            float bx = __ldg(b_out + col), by = __ldg(b_out + col + 1);
#pragma unroll
            for (int q2 = 0; q2 < 2; q2++) {
                int row = r0 + mrow2 + mt * 16 + rq + q2 * 8;
                if (row < n) {
                    float2 o = make_float2(acc2[mt][t][q2 * 2 + 0] + bx,
                                           acc2[mt][t][q2 * 2 + 1] + by);
                    *reinterpret_cast<float2*>(out + (size_t)row * 40 + col) = o;
                }
            }
        }
    }
}

// ---------------------------------------------------------------------------
extern "C" void kernel_launch(void* const* d_in, const int* in_sizes, int n_in,
                              void* d_out, int out_size)
{
    const float* x     = (const float*)d_in[0];
    const int*   ei1   = (const int*)d_in[1];
    const int*   ei2   = (const int*)d_in[2];
    const float* wl1   = (const float*)d_in[3];
    const float* wr1   = (const float*)d_in[4];
    const float* b1    = (const float*)d_in[5];
    const float* wl2   = (const float*)d_in[6];
    const float* wr2   = (const float*)d_in[7];
    const float* b2    = (const float*)d_in[8];
    const float* w_out = (const float*)d_in[9];
    const float* b_out = (const float*)d_in[10];

    int n  = in_sizes[0] / D;
    int E1 = in_sizes[1] / 2;
    int E2 = in_sizes[2] / 2;

    void *p_h1 = nullptr, *p_wth = nullptr, *p_wtl = nullptr;
    void *p_xb = nullptr, *p_h1b = nullptr;
    cudaGetSymbolAddress(&p_h1, g_h1);
    cudaGetSymbolAddress(&p_wth, g_wth);
    cudaGetSymbolAddress(&p_wtl, g_wtl);
    cudaGetSymbolAddress(&p_xb, g_xb);
    cudaGetSymbolAddress(&p_h1b, g_h1b);
    float* h1 = (float*)p_h1;
    const unsigned short* wth = (const unsigned short*)p_wth;
    const unsigned short* wtl = (const unsigned short*)p_wtl;
    const unsigned short* xb  = (const unsigned short*)p_xb;
    const unsigned short* h1b = (const unsigned short*)p_h1b;

    const int LAYER_SMEM = 2 * 64 * HPAD * 2 + 2 * 40 * HPAD * 2;  // 109824 B
    cudaFuncSetAttribute(layer_mma_kernel<0>,
                         cudaFuncAttributeMaxDynamicSharedMemorySize, LAYER_SMEM);
    cudaFuncSetAttribute(layer_mma_kernel<1>,
                         cudaFuncAttributeMaxDynamicSharedMemorySize, LAYER_SMEM);

    int nb_scan = (n + 1023) / 1024;
    int layer_blocks = (n + 63) / 64;
    int gather_blocks = (n * 32 + 255) / 256;

    // ---- prep (zero degs + weight images + convert x) ----
    prep_kernel<<<2048, 256>>>(wl1, wr1, wl2, wr2, w_out, x, n);

    // ---- batched CSR build for both edge lists ----
    count_both_kernel<<<(E1 + E2 + 255) / 256, 256>>>(ei1, ei2, E1, E2);
    scan1_kernel<<<dim3(nb_scan, 2), 1024>>>(n);
    scan23_kernel<<<dim3((n + 255) / 256, 2), 256>>>(n, nb_scan);
    fill_both_kernel<<<(E1 + E2 + 255) / 256, 256>>>(ei1, ei2, E1, E2);

    // ---- layer 1 ----
    gather_b16_kernel<<<gather_blocks, 256>>>(xb, n, 0);
    layer_mma_kernel<0><<<layer_blocks, 256, LAYER_SMEM>>>(
        x, b1, h1, n, wth, wtl, b_out);

    // ---- layer 2 + fused head ----
    gather_b16_kernel<<<gather_blocks, 256>>>(h1b, n, 1);
    layer_mma_kernel<1><<<layer_blocks, 256, LAYER_SMEM>>>(
        h1, b2, (float*)d_out, n, wth + 32768, wtl + 32768, b_out);
}

// round 11
// speedup vs baseline: 1.0482x; 1.0376x over previous
#include <cuda_runtime.h>
#include <cuda_bf16.h>
#include <cstddef>
#include <cstdint>

#define NMAX 100000
#define EMAX 1700000
#define D 128
#define APAD 136   // padded bf16 row stride (main GEMM); 68 words % 32 == 4 -> LDSM conflict-free
#define HPAD 264   // padded bf16 row stride (head phase, K=256); 132 % 32 == 4

// ---------------------------------------------------------------------------
// Scratch (device-global, allocation-free per harness rules)
// ---------------------------------------------------------------------------
__device__ float g_agg[(size_t)NMAX * D];
__device__ float g_h1[(size_t)NMAX * D];
__device__ unsigned short g_h1b[(size_t)NMAX * D];   // bf16 copy of h1
__device__ unsigned short g_xb[(size_t)NMAX * D];    // bf16 copy of x
__device__ int   g_deg[2 * NMAX];
__device__ int   g_off[2 * NMAX];
__device__ int   g_cursor[2 * NMAX];
__device__ int   g_nbr[2 * EMAX];
__device__ int   g_aux[1024];
// bf16 hi/lo layer weight images: [layer][chunk][n_outcol][k]  (transposed)
__device__ unsigned short g_wth[4 * 128 * 128];
__device__ unsigned short g_wtl[4 * 128 * 128];
// bf16 hi/lo head weight images: [n_outcol(40)][k(256)]
__device__ unsigned short g_woth[40 * 256];
__device__ unsigned short g_wotl[40 * 256];

__device__ __forceinline__ unsigned short bfu(__nv_bfloat16 b) {
    return __bfloat16_as_ushort(b);
}

// mma.sync m16n8k16 bf16 (plain-target PTX; HMMA in SASS)
__device__ __forceinline__ void mma16816(float* c, const unsigned* a, const unsigned* b) {
    asm volatile(
        "mma.sync.aligned.m16n8k16.row.col.f32.bf16.bf16.f32 "
        "{%0,%1,%2,%3}, {%4,%5,%6,%7}, {%8,%9}, {%0,%1,%2,%3};"
        : "+f"(c[0]), "+f"(c[1]), "+f"(c[2]), "+f"(c[3])
        : "r"(a[0]), "r"(a[1]), "r"(a[2]), "r"(a[3]), "r"(b[0]), "r"(b[1]));
}

// ldmatrix x4 (plain-target PTX; LDSM in SASS)
#define LDSM4(r, addr) \
    asm volatile("ldmatrix.sync.aligned.m8n8.x4.shared.b16 {%0,%1,%2,%3}, [%4];" \
        : "=r"((r)[0]), "=r"((r)[1]), "=r"((r)[2]), "=r"((r)[3]) : "r"(addr))

__device__ __forceinline__ void split_pack(float x, float y,
                                           unsigned& hp, unsigned& lp) {
    __nv_bfloat16 hx = __float2bfloat16(x);
    __nv_bfloat16 hy = __float2bfloat16(y);
    __nv_bfloat16 lx = __float2bfloat16(x - __bfloat162float(hx));
    __nv_bfloat16 ly = __float2bfloat16(y - __bfloat162float(hy));
    hp = (unsigned)bfu(hx) | ((unsigned)bfu(hy) << 16);
    lp = (unsigned)bfu(lx) | ((unsigned)bfu(ly) << 16);
}

// ---------------------------------------------------------------------------
// prep: weight split/transpose + zero degrees + convert x -> bf16, one kernel
// ---------------------------------------------------------------------------
__global__ void __launch_bounds__(256) prep_kernel(
    const float* __restrict__ wl1, const float* __restrict__ wr1,
    const float* __restrict__ wl2, const float* __restrict__ wr2,
    const float* __restrict__ w_out, const float* __restrict__ x, int n)
{
    int idx = blockIdx.x * 256 + threadIdx.x;
    const int NT = 2048 * 256;
    for (int j = idx; j < 2 * NMAX; j += NT) g_deg[j] = 0;
    for (int i = idx; i < n * 32; i += NT) {
        float4 v = __ldg(reinterpret_cast<const float4*>(x) + i);
        __nv_bfloat162 a = __floats2bfloat162_rn(v.x, v.y);
        __nv_bfloat162 b = __floats2bfloat162_rn(v.z, v.w);
        reinterpret_cast<uint2*>(g_xb)[i] =
            make_uint2(*reinterpret_cast<unsigned*>(&a), *reinterpret_cast<unsigned*>(&b));
    }
    if (idx < 65536) {
        int layer = idx >> 15;
        int rem   = idx & 32767;
        int c     = rem >> 14;
        int nrow  = (rem >> 7) & 127;
        int k     = rem & 127;
        const float* w = layer ? (c ? wr2 : wl2) : (c ? wr1 : wl1);
        float v = __ldg(w + k * 128 + nrow);
        __nv_bfloat16 hb = __float2bfloat16(v);
        __nv_bfloat16 lb = __float2bfloat16(v - __bfloat162float(hb));
        int o = (layer * 2 + c) * 16384 + nrow * 128 + k;
        g_wth[o] = bfu(hb);
        g_wtl[o] = bfu(lb);
    } else if (idx < 75776) {
        int j = idx - 65536;
        int nn = j >> 8;
        int k  = j & 255;
        float v = __ldg(w_out + k * 40 + nn);
        __nv_bfloat16 hb = __float2bfloat16(v);
        __nv_bfloat16 lb = __float2bfloat16(v - __bfloat162float(hb));
        g_woth[nn * 256 + k] = bfu(hb);
        g_wotl[nn * 256 + k] = bfu(lb);
    }
}

// ---------------------------------------------------------------------------
// Merged CSR build for both edge lists
// ---------------------------------------------------------------------------
__global__ void __launch_bounds__(256) count_both_kernel(
    const int* __restrict__ ei1, const int* __restrict__ ei2, int E1, int E2)
{
    int e = blockIdx.x * 256 + threadIdx.x;
    if (e < E1) atomicAdd(&g_deg[__ldg(ei1 + E1 + e)], 1);
    int e2 = e - E1;
    if (e2 >= 0 && e2 < E2) atomicAdd(&g_deg[NMAX + __ldg(ei2 + E2 + e2)], 1);
}

__global__ void __launch_bounds__(1024) scan1_kernel(int n) {
    __shared__ int s[1024];
    int a = blockIdx.y;
    int t = threadIdx.x;
    int i = blockIdx.x * 1024 + t;
    int v = (i < n) ? g_deg[a * NMAX + i] : 0;
    s[t] = v;
    __syncthreads();
#pragma unroll
    for (int d = 1; d < 1024; d <<= 1) {
        int add = (t >= d) ? s[t - d] : 0;
        __syncthreads();
        s[t] += add;
        __syncthreads();
    }
    if (i < n) g_off[a * NMAX + i] = s[t] - v;
    if (t == 1023) g_aux[a * 512 + blockIdx.x] = s[1023];
}

// fused scan2+scan3
__global__ void __launch_bounds__(256) scan23_kernel(int n, int nb) {
    __shared__ int s[128];
    int a = blockIdx.y;
    int i = blockIdx.x * 256 + threadIdx.x;
    int c = blockIdx.x >> 2;
    if (threadIdx.x < nb) s[threadIdx.x] = g_aux[a * 512 + threadIdx.x];
    __syncthreads();
    int pre = 0;
    for (int j = 0; j < c; j++) pre += s[j];
    if (i < n) {
        int o = g_off[a * NMAX + i] + pre;
        g_off[a * NMAX + i] = o;
        g_cursor[a * NMAX + i] = o;
    }
}

__global__ void __launch_bounds__(256) fill_both_kernel(
    const int* __restrict__ ei1, const int* __restrict__ ei2, int E1, int E2)
{
    int e = blockIdx.x * 256 + threadIdx.x;
    if (e < E1) {
        int s = __ldg(ei1 + e);
        int d = __ldg(ei1 + E1 + e);
        int pos = atomicAdd(&g_cursor[d], 1);
        g_nbr[pos] = s;
    }
    int e2 = e - E1;
    if (e2 >= 0 && e2 < E2) {
        int s = __ldg(ei2 + e2);
        int d = __ldg(ei2 + E2 + e2);
        int pos = atomicAdd(&g_cursor[NMAX + d], 1);
        g_nbr[EMAX + pos] = s;
    }
}

// ---------------------------------------------------------------------------
// Gather-mean bf16: fp32 accumulate
// ---------------------------------------------------------------------------
__device__ __forceinline__ void add_bf16x4(float4& acc, uint2 p) {
    float2 a = __bfloat1622float2(*reinterpret_cast<__nv_bfloat162*>(&p.x));
    float2 b = __bfloat1622float2(*reinterpret_cast<__nv_bfloat162*>(&p.y));
    acc.x += a.x; acc.y += a.y; acc.z += b.x; acc.w += b.y;
}

__global__ void __launch_bounds__(256) gather_b16_kernel(
    const unsigned short* __restrict__ featb, int n, int csr)
{
    int v = (blockIdx.x * 256 + threadIdx.x) >> 5;
    int lane = threadIdx.x & 31;
    if (v >= n) return;
    int start = __ldg(g_off + csr * NMAX + v);
    int deg   = __ldg(g_deg + csr * NMAX + v);
    const int* nbr = g_nbr + csr * EMAX;
    const uint2* f = reinterpret_cast<const uint2*>(featb);
    float4 acc = make_float4(0.f, 0.f, 0.f, 0.f);
    int i = 0;
    for (; i + 4 <= deg; i += 4) {
        int s0 = __ldg(nbr + start + i);
        int s1 = __ldg(nbr + start + i + 1);
        int s2 = __ldg(nbr + start + i + 2);
        int s3 = __ldg(nbr + start + i + 3);
        uint2 p0 = __ldg(f + (size_t)s0 * 32 + lane);
        uint2 p1 = __ldg(f + (size_t)s1 * 32 + lane);
        uint2 p2 = __ldg(f + (size_t)s2 * 32 + lane);
        uint2 p3 = __ldg(f + (size_t)s3 * 32 + lane);
        add_bf16x4(acc, p0); add_bf16x4(acc, p1);
        add_bf16x4(acc, p2); add_bf16x4(acc, p3);
    }
    for (; i < deg; i++) {
        int s0 = __ldg(nbr + start + i);
        uint2 p0 = __ldg(f + (size_t)s0 * 32 + lane);
        add_bf16x4(acc, p0);
    }
    float inv = 1.0f / (float)max(deg, 1);
    acc.x *= inv; acc.y *= inv; acc.z *= inv; acc.w *= inv;
    reinterpret_cast<float4*>(g_agg)[(size_t)v * 32 + lane] = acc;
}

// ---------------------------------------------------------------------------
// HMMA SAGE layer with ldmatrix fragment staging.
// MODE 0: out = g_h1 (fp32) + g_h1b (bf16 copy).  relu(agg@wl + xin@wr + b)
// MODE 1: layer-2 + fused head -> out = d_out [n,40].
// ---------------------------------------------------------------------------
template <int MODE>
__global__ void __launch_bounds__(256) layer_mma_kernel(
    const float* __restrict__ xin, const float* __restrict__ bias,
    float* __restrict__ out, int n,
    const unsigned short* __restrict__ wth_base,
    const unsigned short* __restrict__ wtl_base,
    const float* __restrict__ b_out)
{
    extern __shared__ unsigned short sm[];
    unsigned short* s_ah = sm;                       // 64 x APAD
    unsigned short* s_al = sm + 64 * APAD;
    unsigned short* s_wh = sm + 2 * 64 * APAD;       // 128 x APAD
    unsigned short* s_wl = s_wh + 128 * APAD;

    int tid = threadIdx.x, wid = tid >> 5, lane = tid & 31;
    int r0 = blockIdx.x * 64;
    int mrow = (wid & 1) * 32;
    int ncol = (wid >> 1) * 32;
    int rq = lane >> 2;

    // ---- per-lane ldmatrix base addresses (byte, shared space) ----
    unsigned base_ah = (unsigned)__cvta_generic_to_shared(s_ah);
    unsigned base_al = (unsigned)__cvta_generic_to_shared(s_al);
    unsigned base_wh = (unsigned)__cvta_generic_to_shared(s_wh);
    unsigned base_wl = (unsigned)__cvta_generic_to_shared(s_wl);

    int arow = mrow + (lane & 7) + ((lane >> 3) & 1) * 8;   // + mt*16
    int akk  = (lane >> 4) * 8;
    unsigned aOffA = (unsigned)((arow * APAD + akk) * 2);
    unsigned aOffB = (unsigned)(((arow + 16) * APAD + akk) * 2);

    int bn  = ncol + ((lane >> 4) & 1) * 8 + (lane & 7);    // + p*16
    int bkk = ((lane >> 3) & 1) * 8;
    unsigned bOff0 = (unsigned)((bn * APAD + bkk) * 2);
    unsigned bOff1 = (unsigned)(((bn + 16) * APAD + bkk) * 2);

    float acc[2][4][4];
#pragma unroll
    for (int mt = 0; mt < 2; mt++)
#pragma unroll
        for (int nt = 0; nt < 4; nt++)
#pragma unroll
            for (int q = 0; q < 4; q++) acc[mt][nt][q] = 0.f;

    for (int chunk = 0; chunk < 2; chunk++) {
        if (chunk) __syncthreads();   // protect smem reuse

        // ---- stage A (64 rows), fp32 -> bf16 hi/lo split ----
        const float4* src = (chunk == 0) ? reinterpret_cast<const float4*>(g_agg)
                                         : reinterpret_cast<const float4*>(xin);
#pragma unroll
        for (int i = 0; i < 8; i++) {
            int f = tid + i * 256;          // 64 rows * 32 float4
            int row = f >> 5, k4 = f & 31;
            int gr = r0 + row;
            if (gr >= n) gr = n - 1;
            float4 v = __ldg(src + (size_t)gr * 32 + k4);
            unsigned hp0, lp0, hp1, lp1;
            split_pack(v.x, v.y, hp0, lp0);
            split_pack(v.z, v.w, hp1, lp1);
            int o = row * APAD + k4 * 4;
            *reinterpret_cast<uint2*>(s_ah + o) = make_uint2(hp0, hp1);
            *reinterpret_cast<uint2*>(s_al + o) = make_uint2(lp0, lp1);
        }

        // ---- stage W chunk (pre-split transposed images) ----
        {
            const uint2* gh = reinterpret_cast<const uint2*>(wth_base) + chunk * 4096;
            const uint2* gl = reinterpret_cast<const uint2*>(wtl_base) + chunk * 4096;
#pragma unroll
            for (int i = 0; i < 16; i++) {
                int j = tid + i * 256;        // 128 rows * 32 uint2
                int nrow = j >> 5, kk = (j & 31) * 4;
                int o = nrow * APAD + kk;
                *reinterpret_cast<uint2*>(s_wh + o) = __ldg(gh + j);
                *reinterpret_cast<uint2*>(s_wl + o) = __ldg(gl + j);
            }
        }
        __syncthreads();

        // ---- compute: 8 k-steps of m16n8k16, 3 products, LDSM staging ----
#pragma unroll
        for (int s = 0; s < 8; s++) {
            unsigned off = (unsigned)(s * 32);   // 16 bf16 = 32 bytes per k-step
            unsigned bh0[4], bl0[4], bh1[4], bl1[4];
            LDSM4(bh0, base_wh + bOff0 + off);
            LDSM4(bl0, base_wl + bOff0 + off);
            LDSM4(bh1, base_wh + bOff1 + off);
            LDSM4(bl1, base_wl + bOff1 + off);
#pragma unroll
            for (int mt = 0; mt < 2; mt++) {
                unsigned ah[4], al[4];
                LDSM4(ah, base_ah + (mt ? aOffB : aOffA) + off);
                LDSM4(al, base_al + (mt ? aOffB : aOffA) + off);
                mma16816(acc[mt][0], ah, bh0 + 0);
                mma16816(acc[mt][0], ah, bl0 + 0);
                mma16816(acc[mt][0], al, bh0 + 0);
                mma16816(acc[mt][1], ah, bh0 + 2);
                mma16816(acc[mt][1], ah, bl0 + 2);
                mma16816(acc[mt][1], al, bh0 + 2);
                mma16816(acc[mt][2], ah, bh1 + 0);
                mma16816(acc[mt][2], ah, bl1 + 0);
                mma16816(acc[mt][2], al, bh1 + 0);
                mma16816(acc[mt][3], ah, bh1 + 2);
                mma16816(acc[mt][3], ah, bl1 + 2);
                mma16816(acc[mt][3], al, bh1 + 2);
            }
        }
    }

    if (MODE == 0) {
        // ---- epilogue: bias + relu -> g_h1 (fp32) + g_h1b (bf16) ----
#pragma unroll
        for (int mt = 0; mt < 2; mt++) {
#pragma unroll
            for (int nt = 0; nt < 4; nt++) {
                int col = ncol + nt * 8 + (lane & 3) * 2;
                float bx = __ldg(bias + col), by = __ldg(bias + col + 1);
#pragma unroll
                for (int q2 = 0; q2 < 2; q2++) {
                    int row = r0 + mrow + mt * 16 + rq + q2 * 8;
                    if (row < n) {
                        float vx = fmaxf(acc[mt][nt][q2 * 2 + 0] + bx, 0.f);
                        float vy = fmaxf(acc[mt][nt][q2 * 2 + 1] + by, 0.f);
                        *reinterpret_cast<float2*>(out + (size_t)row * 128 + col)
                            = make_float2(vx, vy);
                        __nv_bfloat162 bb = __floats2bfloat162_rn(vx, vy);
                        *reinterpret_cast<unsigned*>(g_h1b + (size_t)row * 128 + col)
                            = *reinterpret_cast<unsigned*>(&bb);
                    }
                }
            }
        }
        return;
    }

    // ================= MODE 1: fused head =================
    __syncthreads();   // everyone done reading main-phase smem

    unsigned short* s_hh = sm;
    unsigned short* s_hl = sm + 64 * HPAD;
    unsigned short* s_oh = sm + 2 * 64 * HPAD;
    unsigned short* s_ol = s_oh + 40 * HPAD;

    // 1) store relu(h2)+bias fragments into cat-tile cols [128..256)
#pragma unroll
    for (int mt = 0; mt < 2; mt++) {
#pragma unroll
        for (int nt = 0; nt < 4; nt++) {
            int col = ncol + nt * 8 + (lane & 3) * 2;
            float bx = __ldg(bias + col), by = __ldg(bias + col + 1);
#pragma unroll
            for (int q2 = 0; q2 < 2; q2++) {
                int row = mrow + mt * 16 + rq + q2 * 8;
                float vx = fmaxf(acc[mt][nt][q2 * 2 + 0] + bx, 0.f);
                float vy = fmaxf(acc[mt][nt][q2 * 2 + 1] + by, 0.f);
                unsigned hp, lp;
                split_pack(vx, vy, hp, lp);
                int o = row * HPAD + 128 + col;
                *reinterpret_cast<unsigned*>(s_hh + o) = hp;
                *reinterpret_cast<unsigned*>(s_hl + o) = lp;
            }
        }
    }

    // 2) load h1 rows (fp32) into cat-tile cols [0..128)
    {
        const float4* h14 = reinterpret_cast<const float4*>(xin);  // xin == g_h1
#pragma unroll
        for (int i = 0; i < 8; i++) {
            int f = tid + i * 256;
            int row = f >> 5, k4 = f & 31;
            int gr = r0 + row;
            if (gr >= n) gr = n - 1;
            float4 v = __ldg(h14 + (size_t)gr * 32 + k4);
            unsigned hp0, lp0, hp1, lp1;
            split_pack(v.x, v.y, hp0, lp0);
            split_pack(v.z, v.w, hp1, lp1);
            int o = row * HPAD + k4 * 4;
            *reinterpret_cast<uint2*>(s_hh + o) = make_uint2(hp0, hp1);
            *reinterpret_cast<uint2*>(s_hl + o) = make_uint2(lp0, lp1);
        }
    }

    // 3) stage w_out images [40 x 256] hi/lo
    {
        const uint2* gh = reinterpret_cast<const uint2*>(g_woth);
        const uint2* gl = reinterpret_cast<const uint2*>(g_wotl);
#pragma unroll
        for (int i = 0; i < 10; i++) {
            int j = tid + i * 256;            // 40*64 = 2560
            if (j < 2560) {
                int nn = j >> 6, kk = (j & 63) * 4;
                int o = nn * HPAD + kk;
                *reinterpret_cast<uint2*>(s_oh + o) = __ldg(gh + j);
                *reinterpret_cast<uint2*>(s_ol + o) = __ldg(gl + j);
            }
        }
    }
    __syncthreads();

    // 4) head GEMM
    int wg = wid >> 1;
    int mrow2 = (wid & 1) * 32;
    int nts0 = wg, nts1 = 4;
    int nnt = (wg == 0) ? 2 : 1;
    int kc_h = (lane & 3) * 2;

    float acc2[2][2][4];
#pragma unroll
    for (int mt = 0; mt < 2; mt++)
#pragma unroll
        for (int t = 0; t < 2; t++)
#pragma unroll
            for (int q = 0; q < 4; q++) acc2[mt][t][q] = 0.f;

#pragma unroll
    for (int s = 0; s < 16; s++) {
        int kc = s * 16 + kc_h;
        unsigned bh[2][2], bl[2][2];
        for (int t = 0; t < nnt; t++) {
            int nt = t ? nts1 : nts0;
            int nn = nt * 8 + rq;
            bh[t][0] = *reinterpret_cast<unsigned*>(s_oh + nn * HPAD + kc);
            bh[t][1] = *reinterpret_cast<unsigned*>(s_oh + nn * HPAD + kc + 8);
            bl[t][0] = *reinterpret_cast<unsigned*>(s_ol + nn * HPAD + kc);
            bl[t][1] = *reinterpret_cast<unsigned*>(s_ol + nn * HPAD + kc + 8);
        }
#pragma unroll
        for (int mt = 0; mt < 2; mt++) {
            int rr = mrow2 + mt * 16 + rq;
            unsigned ah[4], al[4];
            ah[0] = *reinterpret_cast<unsigned*>(s_hh + rr * HPAD + kc);
            ah[1] = *reinterpret_cast<unsigned*>(s_hh + (rr + 8) * HPAD + kc);
            ah[2] = *reinterpret_cast<unsigned*>(s_hh + rr * HPAD + kc + 8);
            ah[3] = *reinterpret_cast<unsigned*>(s_hh + (rr + 8) * HPAD + kc + 8);
            al[0] = *reinterpret_cast<unsigned*>(s_hl + rr * HPAD + kc);
            al[1] = *reinterpret_cast<unsigned*>(s_hl + (rr + 8) * HPAD + kc);
            al[2] = *reinterpret_cast<unsigned*>(s_hl + rr * HPAD + kc + 8);
            al[3] = *reinterpret_cast<unsigned*>(s_hl + (rr + 8) * HPAD + kc + 8);
            for (int t = 0; t < nnt; t++) {
                mma16816(acc2[mt][t], ah, bh[t]);
                mma16816(acc2[mt][t], ah, bl[t]);
                mma16816(acc2[mt][t], al, bh[t]);
            }
        }
    }

    // 5) write d_out
#pragma unroll
    for (int mt = 0; mt < 2; mt++) {
        for (int t = 0; t < nnt; t++) {
            int nt = t ? nts1 : nts0;
            int col = nt * 8 + (lane & 3) * 2;
            float bx = __ldg(b_out + col), by = __ldg(b_out + col + 1);
#pragma unroll
            for (int q2 = 0; q2 < 2; q2++) {
                int row = r0 + mrow2 + mt * 16 + rq + q2 * 8;
                if (row < n) {
                    float2 o = make_float2(acc2[mt][t][q2 * 2 + 0] + bx,
                                           acc2[mt][t][q2 * 2 + 1] + by);
                    *reinterpret_cast<float2*>(out + (size_t)row * 40 + col) = o;
                }
            }
        }
    }
}

// ---------------------------------------------------------------------------
extern "C" void kernel_launch(void* const* d_in, const int* in_sizes, int n_in,
                              void* d_out, int out_size)
{
    const float* x     = (const float*)d_in[0];
    const int*   ei1   = (const int*)d_in[1];
    const int*   ei2   = (const int*)d_in[2];
    const float* wl1   = (const float*)d_in[3];
    const float* wr1   = (const float*)d_in[4];
    const float* b1    = (const float*)d_in[5];
    const float* wl2   = (const float*)d_in[6];
    const float* wr2   = (const float*)d_in[7];
    const float* b2    = (const float*)d_in[8];
    const float* w_out = (const float*)d_in[9];
    const float* b_out = (const float*)d_in[10];

    int n  = in_sizes[0] / D;
    int E1 = in_sizes[1] / 2;
    int E2 = in_sizes[2] / 2;

    void *p_h1 = nullptr, *p_wth = nullptr, *p_wtl = nullptr;
    void *p_xb = nullptr, *p_h1b = nullptr;
    cudaGetSymbolAddress(&p_h1, g_h1);
    cudaGetSymbolAddress(&p_wth, g_wth);
    cudaGetSymbolAddress(&p_wtl, g_wtl);
    cudaGetSymbolAddress(&p_xb, g_xb);
    cudaGetSymbolAddress(&p_h1b, g_h1b);
    float* h1 = (float*)p_h1;
    const unsigned short* wth = (const unsigned short*)p_wth;
    const unsigned short* wtl = (const unsigned short*)p_wtl;
    const unsigned short* xb  = (const unsigned short*)p_xb;
    const unsigned short* h1b = (const unsigned short*)p_h1b;

    // max(main phase 104448, head phase 109824)
    const int LAYER_SMEM = 2 * 64 * HPAD * 2 + 2 * 40 * HPAD * 2;  // 109824 B
    cudaFuncSetAttribute(layer_mma_kernel<0>,
                         cudaFuncAttributeMaxDynamicSharedMemorySize, LAYER_SMEM);
    cudaFuncSetAttribute(layer_mma_kernel<1>,
                         cudaFuncAttributeMaxDynamicSharedMemorySize, LAYER_SMEM);

    int nb_scan = (n + 1023) / 1024;
    int layer_blocks = (n + 63) / 64;
    int gather_blocks = (n * 32 + 255) / 256;

    // ---- prep (zero degs + weight images + convert x) ----
    prep_kernel<<<2048, 256>>>(wl1, wr1, wl2, wr2, w_out, x, n);

    // ---- batched CSR build for both edge lists ----
    count_both_kernel<<<(E1 + E2 + 255) / 256, 256>>>(ei1, ei2, E1, E2);
    scan1_kernel<<<dim3(nb_scan, 2), 1024>>>(n);
    scan23_kernel<<<dim3((n + 255) / 256, 2), 256>>>(n, nb_scan);
    fill_both_kernel<<<(E1 + E2 + 255) / 256, 256>>>(ei1, ei2, E1, E2);

    // ---- layer 1 ----
    gather_b16_kernel<<<gather_blocks, 256>>>(xb, n, 0);
    layer_mma_kernel<0><<<layer_blocks, 256, LAYER_SMEM>>>(
        x, b1, h1, n, wth, wtl, b_out);

    // ---- layer 2 + fused head ----
    gather_b16_kernel<<<gather_blocks, 256>>>(h1b, n, 1);
    layer_mma_kernel<1><<<layer_blocks, 256, LAYER_SMEM>>>(
        h1, b2, (float*)d_out, n, wth + 32768, wtl + 32768, b_out);
}

// round 12
// speedup vs baseline: 1.0818x; 1.0321x over previous
#include <cuda_runtime.h>
#include <cuda_bf16.h>
#include <cuda_fp16.h>
#include <cstddef>
#include <cstdint>

#define NMAX 100000
#define EMAX 1700000
#define D 128
#define APAD 136   // padded 16-bit row stride (main GEMM); 68 words % 32 == 4 -> LDSM conflict-free
#define HPAD 264   // padded bf16 row stride (head phase, K=256); 132 % 32 == 4

// ---------------------------------------------------------------------------
// Scratch (device-global, allocation-free per harness rules)
// ---------------------------------------------------------------------------
__device__ float g_agg[(size_t)NMAX * D];
__device__ float g_h1[(size_t)NMAX * D];
__device__ unsigned short g_h1b[(size_t)NMAX * D];   // bf16 copy of h1
__device__ unsigned short g_xb[(size_t)NMAX * D];    // bf16 copy of x
__device__ int   g_deg[2 * NMAX];
__device__ int   g_off[2 * NMAX];
__device__ int   g_cursor[2 * NMAX];
__device__ int   g_nbr[2 * EMAX];
__device__ int   g_aux[1024];
// fp16 hi/lo layer weight images: [layer][chunk][n_outcol][k]  (transposed)
__device__ unsigned short g_wth[4 * 128 * 128];
__device__ unsigned short g_wtl[4 * 128 * 128];
// bf16 hi/lo head weight images: [n_outcol(40)][k(256)]
__device__ unsigned short g_woth[40 * 256];
__device__ unsigned short g_wotl[40 * 256];

__device__ __forceinline__ unsigned short bfu(__nv_bfloat16 b) {
    return __bfloat16_as_ushort(b);
}

// mma.sync m16n8k16 fp16 inputs, fp32 accum (plain-target PTX; HMMA in SASS)
__device__ __forceinline__ void mma16816h(float* c, const unsigned* a, const unsigned* b) {
    asm volatile(
        "mma.sync.aligned.m16n8k16.row.col.f32.f16.f16.f32 "
        "{%0,%1,%2,%3}, {%4,%5,%6,%7}, {%8,%9}, {%0,%1,%2,%3};"
        : "+f"(c[0]), "+f"(c[1]), "+f"(c[2]), "+f"(c[3])
        : "r"(a[0]), "r"(a[1]), "r"(a[2]), "r"(a[3]), "r"(b[0]), "r"(b[1]));
}

// mma.sync m16n8k16 bf16 (head phase)
__device__ __forceinline__ void mma16816(float* c, const unsigned* a, const unsigned* b) {
    asm volatile(
        "mma.sync.aligned.m16n8k16.row.col.f32.bf16.bf16.f32 "
        "{%0,%1,%2,%3}, {%4,%5,%6,%7}, {%8,%9}, {%0,%1,%2,%3};"
        : "+f"(c[0]), "+f"(c[1]), "+f"(c[2]), "+f"(c[3])
        : "r"(a[0]), "r"(a[1]), "r"(a[2]), "r"(a[3]), "r"(b[0]), "r"(b[1]));
}

// ldmatrix x4 (LDSM in SASS)
#define LDSM4(r, addr) \
    asm volatile("ldmatrix.sync.aligned.m8n8.x4.shared.b16 {%0,%1,%2,%3}, [%4];" \
        : "=r"((r)[0]), "=r"((r)[1]), "=r"((r)[2]), "=r"((r)[3]) : "r"(addr))

__device__ __forceinline__ void split_pack(float x, float y,
                                           unsigned& hp, unsigned& lp) {
    __nv_bfloat16 hx = __float2bfloat16(x);
    __nv_bfloat16 hy = __float2bfloat16(y);
    __nv_bfloat16 lx = __float2bfloat16(x - __bfloat162float(hx));
    __nv_bfloat16 ly = __float2bfloat16(y - __bfloat162float(hy));
    hp = (unsigned)bfu(hx) | ((unsigned)bfu(hy) << 16);
    lp = (unsigned)bfu(lx) | ((unsigned)bfu(ly) << 16);
}

// ---------------------------------------------------------------------------
// prep: weight split/transpose + zero degrees + convert x -> bf16, one kernel
// Layer weights: fp16 hi + fp16 residual (exact 2-term representation).
// ---------------------------------------------------------------------------
__global__ void __launch_bounds__(256) prep_kernel(
    const float* __restrict__ wl1, const float* __restrict__ wr1,
    const float* __restrict__ wl2, const float* __restrict__ wr2,
    const float* __restrict__ w_out, const float* __restrict__ x, int n)
{
    int idx = blockIdx.x * 256 + threadIdx.x;
    const int NT = 2048 * 256;
    for (int j = idx; j < 2 * NMAX; j += NT) g_deg[j] = 0;
    for (int i = idx; i < n * 32; i += NT) {
        float4 v = __ldg(reinterpret_cast<const float4*>(x) + i);
        __nv_bfloat162 a = __floats2bfloat162_rn(v.x, v.y);
        __nv_bfloat162 b = __floats2bfloat162_rn(v.z, v.w);
        reinterpret_cast<uint2*>(g_xb)[i] =
            make_uint2(*reinterpret_cast<unsigned*>(&a), *reinterpret_cast<unsigned*>(&b));
    }
    if (idx < 65536) {
        int layer = idx >> 15;
        int rem   = idx & 32767;
        int c     = rem >> 14;
        int nrow  = (rem >> 7) & 127;
        int k     = rem & 127;
        const float* w = layer ? (c ? wr2 : wl2) : (c ? wr1 : wl1);
        float v = __ldg(w + k * 128 + nrow);
        __half hb = __float2half_rn(v);
        __half lb = __float2half_rn(v - __half2float(hb));
        int o = (layer * 2 + c) * 16384 + nrow * 128 + k;
        g_wth[o] = __half_as_ushort(hb);
        g_wtl[o] = __half_as_ushort(lb);
    } else if (idx < 75776) {
        int j = idx - 65536;
        int nn = j >> 8;
        int k  = j & 255;
        float v = __ldg(w_out + k * 40 + nn);
        __nv_bfloat16 hb = __float2bfloat16(v);
        __nv_bfloat16 lb = __float2bfloat16(v - __bfloat162float(hb));
        g_woth[nn * 256 + k] = bfu(hb);
        g_wotl[nn * 256 + k] = bfu(lb);
    }
}

// ---------------------------------------------------------------------------
// Merged CSR build for both edge lists
// ---------------------------------------------------------------------------
__global__ void __launch_bounds__(256) count_both_kernel(
    const int* __restrict__ ei1, const int* __restrict__ ei2, int E1, int E2)
{
    int e = blockIdx.x * 256 + threadIdx.x;
    if (e < E1) atomicAdd(&g_deg[__ldg(ei1 + E1 + e)], 1);
    int e2 = e - E1;
    if (e2 >= 0 && e2 < E2) atomicAdd(&g_deg[NMAX + __ldg(ei2 + E2 + e2)], 1);
}

__global__ void __launch_bounds__(1024) scan1_kernel(int n) {
    __shared__ int s[1024];
    int a = blockIdx.y;
    int t = threadIdx.x;
    int i = blockIdx.x * 1024 + t;
    int v = (i < n) ? g_deg[a * NMAX + i] : 0;
    s[t] = v;
    __syncthreads();
#pragma unroll
    for (int d = 1; d < 1024; d <<= 1) {
        int add = (t >= d) ? s[t - d] : 0;
        __syncthreads();
        s[t] += add;
        __syncthreads();
    }
    if (i < n) g_off[a * NMAX + i] = s[t] - v;
    if (t == 1023) g_aux[a * 512 + blockIdx.x] = s[1023];
}

// fused scan2+scan3
__global__ void __launch_bounds__(256) scan23_kernel(int n, int nb) {
    __shared__ int s[128];
    int a = blockIdx.y;
    int i = blockIdx.x * 256 + threadIdx.x;
    int c = blockIdx.x >> 2;
    if (threadIdx.x < nb) s[threadIdx.x] = g_aux[a * 512 + threadIdx.x];
    __syncthreads();
    int pre = 0;
    for (int j = 0; j < c; j++) pre += s[j];
    if (i < n) {
        int o = g_off[a * NMAX + i] + pre;
        g_off[a * NMAX + i] = o;
        g_cursor[a * NMAX + i] = o;
    }
}

__global__ void __launch_bounds__(256) fill_both_kernel(
    const int* __restrict__ ei1, const int* __restrict__ ei2, int E1, int E2)
{
    int e = blockIdx.x * 256 + threadIdx.x;
    if (e < E1) {
        int s = __ldg(ei1 + e);
        int d = __ldg(ei1 + E1 + e);
        int pos = atomicAdd(&g_cursor[d], 1);
        g_nbr[pos] = s;
    }
    int e2 = e - E1;
    if (e2 >= 0 && e2 < E2) {
        int s = __ldg(ei2 + e2);
        int d = __ldg(ei2 + E2 + e2);
        int pos = atomicAdd(&g_cursor[NMAX + d], 1);
        g_nbr[EMAX + pos] = s;
    }
}

// ---------------------------------------------------------------------------
// Gather-mean bf16: fp32 accumulate
// ---------------------------------------------------------------------------
__device__ __forceinline__ void add_bf16x4(float4& acc, uint2 p) {
    float2 a = __bfloat1622float2(*reinterpret_cast<__nv_bfloat162*>(&p.x));
    float2 b = __bfloat1622float2(*reinterpret_cast<__nv_bfloat162*>(&p.y));
    acc.x += a.x; acc.y += a.y; acc.z += b.x; acc.w += b.y;
}

__global__ void __launch_bounds__(256) gather_b16_kernel(
    const unsigned short* __restrict__ featb, int n, int csr)
{
    int v = (blockIdx.x * 256 + threadIdx.x) >> 5;
    int lane = threadIdx.x & 31;
    if (v >= n) return;
    int start = __ldg(g_off + csr * NMAX + v);
    int deg   = __ldg(g_deg + csr * NMAX + v);
    const int* nbr = g_nbr + csr * EMAX;
    const uint2* f = reinterpret_cast<const uint2*>(featb);
    float4 acc = make_float4(0.f, 0.f, 0.f, 0.f);
    int i = 0;
    for (; i + 4 <= deg; i += 4) {
        int s0 = __ldg(nbr + start + i);
        int s1 = __ldg(nbr + start + i + 1);
        int s2 = __ldg(nbr + start + i + 2);
        int s3 = __ldg(nbr + start + i + 3);
        uint2 p0 = __ldg(f + (size_t)s0 * 32 + lane);
        uint2 p1 = __ldg(f + (size_t)s1 * 32 + lane);
        uint2 p2 = __ldg(f + (size_t)s2 * 32 + lane);
        uint2 p3 = __ldg(f + (size_t)s3 * 32 + lane);
        add_bf16x4(acc, p0); add_bf16x4(acc, p1);
        add_bf16x4(acc, p2); add_bf16x4(acc, p3);
    }
    for (; i < deg; i++) {
        int s0 = __ldg(nbr + start + i);
        uint2 p0 = __ldg(f + (size_t)s0 * 32 + lane);
        add_bf16x4(acc, p0);
    }
    float inv = 1.0f / (float)max(deg, 1);
    acc.x *= inv; acc.y *= inv; acc.z *= inv; acc.w *= inv;
    reinterpret_cast<float4*>(g_agg)[(size_t)v * 32 + lane] = acc;
}

// ---------------------------------------------------------------------------
// HMMA SAGE layer: fp16 2-product main GEMM (A rounded fp16, W exact fp16 split)
// MODE 0: out = g_h1 (fp32) + g_h1b (bf16 copy).  relu(agg@wl + xin@wr + b)
// MODE 1: layer-2 + fused head (bf16 3-product) -> out = d_out [n,40].
// ---------------------------------------------------------------------------
template <int MODE>
__global__ void __launch_bounds__(256) layer_mma_kernel(
    const float* __restrict__ xin, const float* __restrict__ bias,
    float* __restrict__ out, int n,
    const unsigned short* __restrict__ wth_base,
    const unsigned short* __restrict__ wtl_base,
    const float* __restrict__ b_out)
{
    extern __shared__ unsigned short sm[];
    unsigned short* s_a  = sm;                       // 64 x APAD (fp16)
    unsigned short* s_wh = sm + 64 * APAD;           // 128 x APAD
    unsigned short* s_wl = s_wh + 128 * APAD;

    int tid = threadIdx.x, wid = tid >> 5, lane = tid & 31;
    int r0 = blockIdx.x * 64;
    int mrow = (wid & 1) * 32;
    int ncol = (wid >> 1) * 32;
    int rq = lane >> 2;

    // ---- per-lane ldmatrix base addresses ----
    unsigned base_a  = (unsigned)__cvta_generic_to_shared(s_a);
    unsigned base_wh = (unsigned)__cvta_generic_to_shared(s_wh);
    unsigned base_wl = (unsigned)__cvta_generic_to_shared(s_wl);

    int arow = mrow + (lane & 7) + ((lane >> 3) & 1) * 8;   // + mt*16
    int akk  = (lane >> 4) * 8;
    unsigned aOffA = (unsigned)((arow * APAD + akk) * 2);
    unsigned aOffB = (unsigned)(((arow + 16) * APAD + akk) * 2);

    int bn  = ncol + ((lane >> 4) & 1) * 8 + (lane & 7);    // + p*16
    int bkk = ((lane >> 3) & 1) * 8;
    unsigned bOff0 = (unsigned)((bn * APAD + bkk) * 2);
    unsigned bOff1 = (unsigned)(((bn + 16) * APAD + bkk) * 2);

    float acc[2][4][4];
#pragma unroll
    for (int mt = 0; mt < 2; mt++)
#pragma unroll
        for (int nt = 0; nt < 4; nt++)
#pragma unroll
            for (int q = 0; q < 4; q++) acc[mt][nt][q] = 0.f;

    for (int chunk = 0; chunk < 2; chunk++) {
        if (chunk) __syncthreads();   // protect smem reuse

        // ---- stage A (64 rows), fp32 -> fp16 (single) ----
        const float4* src = (chunk == 0) ? reinterpret_cast<const float4*>(g_agg)
                                         : reinterpret_cast<const float4*>(xin);
#pragma unroll
        for (int i = 0; i < 8; i++) {
            int f = tid + i * 256;          // 64 rows * 32 float4
            int row = f >> 5, k4 = f & 31;
            int gr = r0 + row;
            if (gr >= n) gr = n - 1;
            float4 v = __ldg(src + (size_t)gr * 32 + k4);
            __half2 h01 = __floats2half2_rn(v.x, v.y);
            __half2 h23 = __floats2half2_rn(v.z, v.w);
            int o = row * APAD + k4 * 4;
            *reinterpret_cast<uint2*>(s_a + o) =
                make_uint2(*reinterpret_cast<unsigned*>(&h01),
                           *reinterpret_cast<unsigned*>(&h23));
        }

        // ---- stage W chunk (pre-split fp16 transposed images) ----
        {
            const uint2* gh = reinterpret_cast<const uint2*>(wth_base) + chunk * 4096;
            const uint2* gl = reinterpret_cast<const uint2*>(wtl_base) + chunk * 4096;
#pragma unroll
            for (int i = 0; i < 16; i++) {
                int j = tid + i * 256;        // 128 rows * 32 uint2
                int nrow = j >> 5, kk = (j & 31) * 4;
                int o = nrow * APAD + kk;
                *reinterpret_cast<uint2*>(s_wh + o) = __ldg(gh + j);
                *reinterpret_cast<uint2*>(s_wl + o) = __ldg(gl + j);
            }
        }
        __syncthreads();

        // ---- compute: 8 k-steps of m16n8k16, 2 products, LDSM staging ----
#pragma unroll
        for (int s = 0; s < 8; s++) {
            unsigned off = (unsigned)(s * 32);   // 16 halves = 32 bytes per k-step
            unsigned bh0[4], bl0[4], bh1[4], bl1[4];
            LDSM4(bh0, base_wh + bOff0 + off);
            LDSM4(bl0, base_wl + bOff0 + off);
            LDSM4(bh1, base_wh + bOff1 + off);
            LDSM4(bl1, base_wl + bOff1 + off);
#pragma unroll
            for (int mt = 0; mt < 2; mt++) {
                unsigned a[4];
                LDSM4(a, base_a + (mt ? aOffB : aOffA) + off);
                mma16816h(acc[mt][0], a, bh0 + 0);
                mma16816h(acc[mt][0], a, bl0 + 0);
                mma16816h(acc[mt][1], a, bh0 + 2);
                mma16816h(acc[mt][1], a, bl0 + 2);
                mma16816h(acc[mt][2], a, bh1 + 0);
                mma16816h(acc[mt][2], a, bl1 + 0);
                mma16816h(acc[mt][3], a, bh1 + 2);
                mma16816h(acc[mt][3], a, bl1 + 2);
            }
        }
    }

    if (MODE == 0) {
        // ---- epilogue: bias + relu -> g_h1 (fp32) + g_h1b (bf16) ----
#pragma unroll
        for (int mt = 0; mt < 2; mt++) {
#pragma unroll
            for (int nt = 0; nt < 4; nt++) {
                int col = ncol + nt * 8 + (lane & 3) * 2;
                float bx = __ldg(bias + col), by = __ldg(bias + col + 1);
#pragma unroll
                for (int q2 = 0; q2 < 2; q2++) {
                    int row = r0 + mrow + mt * 16 + rq + q2 * 8;
                    if (row < n) {
                        float vx = fmaxf(acc[mt][nt][q2 * 2 + 0] + bx, 0.f);
                        float vy = fmaxf(acc[mt][nt][q2 * 2 + 1] + by, 0.f);
                        *reinterpret_cast<float2*>(out + (size_t)row * 128 + col)
                            = make_float2(vx, vy);
                        __nv_bfloat162 bb = __floats2bfloat162_rn(vx, vy);
                        *reinterpret_cast<unsigned*>(g_h1b + (size_t)row * 128 + col)
                            = *reinterpret_cast<unsigned*>(&bb);
                    }
                }
            }
        }
        return;
    }

    // ================= MODE 1: fused head (bf16 3-product) =================
    __syncthreads();   // everyone done reading main-phase smem

    unsigned short* s_hh = sm;
    unsigned short* s_hl = sm + 64 * HPAD;
    unsigned short* s_oh = sm + 2 * 64 * HPAD;
    unsigned short* s_ol = s_oh + 40 * HPAD;

    // 1) store relu(h2)+bias fragments into cat-tile cols [128..256)
#pragma unroll
    for (int mt = 0; mt < 2; mt++) {
#pragma unroll
        for (int nt = 0; nt < 4; nt++) {
            int col = ncol + nt * 8 + (lane & 3) * 2;
            float bx = __ldg(bias + col), by = __ldg(bias + col + 1);
#pragma unroll
            for (int q2 = 0; q2 < 2; q2++) {
                int row = mrow + mt * 16 + rq + q2 * 8;
                float vx = fmaxf(acc[mt][nt][q2 * 2 + 0] + bx, 0.f);
                float vy = fmaxf(acc[mt][nt][q2 * 2 + 1] + by, 0.f);
                unsigned hp, lp;
                split_pack(vx, vy, hp, lp);
                int o = row * HPAD + 128 + col;
                *reinterpret_cast<unsigned*>(s_hh + o) = hp;
                *reinterpret_cast<unsigned*>(s_hl + o) = lp;
            }
        }
    }

    // 2) load h1 rows (fp32) into cat-tile cols [0..128)
    {
        const float4* h14 = reinterpret_cast<const float4*>(xin);  // xin == g_h1
#pragma unroll
        for (int i = 0; i < 8; i++) {
            int f = tid + i * 256;
            int row = f >> 5, k4 = f & 31;
            int gr = r0 + row;
            if (gr >= n) gr = n - 1;
            float4 v = __ldg(h14 + (size_t)gr * 32 + k4);
            unsigned hp0, lp0, hp1, lp1;
            split_pack(v.x, v.y, hp0, lp0);
            split_pack(v.z, v.w, hp1, lp1);
            int o = row * HPAD + k4 * 4;
            *reinterpret_cast<uint2*>(s_hh + o) = make_uint2(hp0, hp1);
            *reinterpret_cast<uint2*>(s_hl + o) = make_uint2(lp0, lp1);
        }
    }

    // 3) stage w_out images [40 x 256] hi/lo
    {
        const uint2* gh = reinterpret_cast<const uint2*>(g_woth);
        const uint2* gl = reinterpret_cast<const uint2*>(g_wotl);
#pragma unroll
        for (int i = 0; i < 10; i++) {
            int j = tid + i * 256;            // 40*64 = 2560
            if (j < 2560) {
                int nn = j >> 6, kk = (j & 63) * 4;
                int o = nn * HPAD + kk;
                *reinterpret_cast<uint2*>(s_oh + o) = __ldg(gh + j);
                *reinterpret_cast<uint2*>(s_ol + o) = __ldg(gl + j);
            }
        }
    }
    __syncthreads();

    // 4) head GEMM
    int wg = wid >> 1;
    int mrow2 = (wid & 1) * 32;
    int nts0 = wg, nts1 = 4;
    int nnt = (wg == 0) ? 2 : 1;
    int kc_h = (lane & 3) * 2;

    float acc2[2][2][4];
#pragma unroll
    for (int mt = 0; mt < 2; mt++)
#pragma unroll
        for (int t = 0; t < 2; t++)
#pragma unroll
            for (int q = 0; q < 4; q++) acc2[mt][t][q] = 0.f;

#pragma unroll
    for (int s = 0; s < 16; s++) {
        int kc = s * 16 + kc_h;
        unsigned bh[2][2], bl[2][2];
        for (int t = 0; t < nnt; t++) {
            int nt = t ? nts1 : nts0;
            int nn = nt * 8 + rq;
            bh[t][0] = *reinterpret_cast<unsigned*>(s_oh + nn * HPAD + kc);
            bh[t][1] = *reinterpret_cast<unsigned*>(s_oh + nn * HPAD + kc + 8);
            bl[t][0] = *reinterpret_cast<unsigned*>(s_ol + nn * HPAD + kc);
            bl[t][1] = *reinterpret_cast<unsigned*>(s_ol + nn * HPAD + kc + 8);
        }
#pragma unroll
        for (int mt = 0; mt < 2; mt++) {
            int rr = mrow2 + mt * 16 + rq;
            unsigned ah[4], al[4];
            ah[0] = *reinterpret_cast<unsigned*>(s_hh + rr * HPAD + kc);
            ah[1] = *reinterpret_cast<unsigned*>(s_hh + (rr + 8) * HPAD + kc);
            ah[2] = *reinterpret_cast<unsigned*>(s_hh + rr * HPAD + kc + 8);
            ah[3] = *reinterpret_cast<unsigned*>(s_hh + (rr + 8) * HPAD + kc + 8);
            al[0] = *reinterpret_cast<unsigned*>(s_hl + rr * HPAD + kc);
            al[1] = *reinterpret_cast<unsigned*>(s_hl + (rr + 8) * HPAD + kc);
            al[2] = *reinterpret_cast<unsigned*>(s_hl + rr * HPAD + kc + 8);
            al[3] = *reinterpret_cast<unsigned*>(s_hl + (rr + 8) * HPAD + kc + 8);
            for (int t = 0; t < nnt; t++) {
                mma16816(acc2[mt][t], ah, bh[t]);
                mma16816(acc2[mt][t], ah, bl[t]);
                mma16816(acc2[mt][t], al, bh[t]);
            }
        }
    }

    // 5) write d_out
#pragma unroll
    for (int mt = 0; mt < 2; mt++) {
        for (int t = 0; t < nnt; t++) {
            int nt = t ? nts1 : nts0;
            int col = nt * 8 + (lane & 3) * 2;
            float bx = __ldg(b_out + col), by = __ldg(b_out + col + 1);
#pragma unroll
            for (int q2 = 0; q2 < 2; q2++) {
                int row = r0 + mrow2 + mt * 16 + rq + q2 * 8;
                if (row < n) {
                    float2 o = make_float2(acc2[mt][t][q2 * 2 + 0] + bx,
                                           acc2[mt][t][q2 * 2 + 1] + by);
                    *reinterpret_cast<float2*>(out + (size_t)row * 40 + col) = o;
                }
            }
        }
    }
}

// ---------------------------------------------------------------------------
extern "C" void kernel_launch(void* const* d_in, const int* in_sizes, int n_in,
                              void* d_out, int out_size)
{
    const float* x     = (const float*)d_in[0];
    const int*   ei1   = (const int*)d_in[1];
    const int*   ei2   = (const int*)d_in[2];
    const float* wl1   = (const float*)d_in[3];
    const float* wr1   = (const float*)d_in[4];
    const float* b1    = (const float*)d_in[5];
    const float* wl2   = (const float*)d_in[6];
    const float* wr2   = (const float*)d_in[7];
    const float* b2    = (const float*)d_in[8];
    const float* w_out = (const float*)d_in[9];
    const float* b_out = (const float*)d_in[10];

    int n  = in_sizes[0] / D;
    int E1 = in_sizes[1] / 2;
    int E2 = in_sizes[2] / 2;

    void *p_h1 = nullptr, *p_wth = nullptr, *p_wtl = nullptr;
    void *p_xb = nullptr, *p_h1b = nullptr;
    cudaGetSymbolAddress(&p_h1, g_h1);
    cudaGetSymbolAddress(&p_wth, g_wth);
    cudaGetSymbolAddress(&p_wtl, g_wtl);
    cudaGetSymbolAddress(&p_xb, g_xb);
    cudaGetSymbolAddress(&p_h1b, g_h1b);
    float* h1 = (float*)p_h1;
    const unsigned short* wth = (const unsigned short*)p_wth;
    const unsigned short* wtl = (const unsigned short*)p_wtl;
    const unsigned short* xb  = (const unsigned short*)p_xb;
    const unsigned short* h1b = (const unsigned short*)p_h1b;

    // max(main phase 87040, head phase 109824)
    const int LAYER_SMEM = 2 * 64 * HPAD * 2 + 2 * 40 * HPAD * 2;  // 109824 B
    cudaFuncSetAttribute(layer_mma_kernel<0>,
                         cudaFuncAttributeMaxDynamicSharedMemorySize, LAYER_SMEM);
    cudaFuncSetAttribute(layer_mma_kernel<1>,
                         cudaFuncAttributeMaxDynamicSharedMemorySize, LAYER_SMEM);

    int nb_scan = (n + 1023) / 1024;
    int layer_blocks = (n + 63) / 64;
    int gather_blocks = (n * 32 + 255) / 256;

    // ---- prep (zero degs + weight images + convert x) ----
    prep_kernel<<<2048, 256>>>(wl1, wr1, wl2, wr2, w_out, x, n);

    // ---- batched CSR build for both edge lists ----
    count_both_kernel<<<(E1 + E2 + 255) / 256, 256>>>(ei1, ei2, E1, E2);
    scan1_kernel<<<dim3(nb_scan, 2), 1024>>>(n);
    scan23_kernel<<<dim3((n + 255) / 256, 2), 256>>>(n, nb_scan);
    fill_both_kernel<<<(E1 + E2 + 255) / 256, 256>>>(ei1, ei2, E1, E2);

    // ---- layer 1 ----
    gather_b16_kernel<<<gather_blocks, 256>>>(xb, n, 0);
    layer_mma_kernel<0><<<layer_blocks, 256, LAYER_SMEM>>>(
        x, b1, h1, n, wth, wtl, b_out);

    // ---- layer 2 + fused head ----
    gather_b16_kernel<<<gather_blocks, 256>>>(h1b, n, 1);
    layer_mma_kernel<1><<<layer_blocks, 256, LAYER_SMEM>>>(
        h1, b2, (float*)d_out, n, wth + 32768, wtl + 32768, b_out);
}

// round 13
// speedup vs baseline: 1.3399x; 1.2386x over previous
#include <cuda_runtime.h>
#include <cuda_bf16.h>
#include <cuda_fp16.h>
#include <cstddef>
#include <cstdint>

#define NMAX 100000
#define EMAX 1700000
#define D 128
#define APAD 136   // padded 16-bit row stride (main GEMM); 68 words % 32 == 4 -> LDSM conflict-free
#define HPAD 264   // padded row stride (head phase, K=256)

// ---------------------------------------------------------------------------
// Scratch (device-global, allocation-free per harness rules)
// ---------------------------------------------------------------------------
__device__ float g_agg[(size_t)NMAX * D];
__device__ float g_h1[(size_t)NMAX * D];
__device__ unsigned short g_h1b[(size_t)NMAX * D];   // bf16 copy of h1
__device__ unsigned short g_xb[(size_t)NMAX * D];    // bf16 copy of x
__device__ int   g_deg[2 * NMAX];
__device__ int   g_off[2 * NMAX];
__device__ int   g_cursor[2 * NMAX];
__device__ int   g_nbr[2 * EMAX];
__device__ int   g_aux[1024];
// fp16 layer weight images (single, rounded): [layer][chunk][n_outcol][k]
__device__ unsigned short g_wth[4 * 128 * 128];
// fp16 hi/lo head weight images (exact 2-term): [n_outcol(40)][k(256)]
__device__ unsigned short g_woth[40 * 256];
__device__ unsigned short g_wotl[40 * 256];

// mma.sync m16n8k16 fp16 inputs, fp32 accum (plain-target PTX; HMMA in SASS)
__device__ __forceinline__ void mma16816h(float* c, const unsigned* a, const unsigned* b) {
    asm volatile(
        "mma.sync.aligned.m16n8k16.row.col.f32.f16.f16.f32 "
        "{%0,%1,%2,%3}, {%4,%5,%6,%7}, {%8,%9}, {%0,%1,%2,%3};"
        : "+f"(c[0]), "+f"(c[1]), "+f"(c[2]), "+f"(c[3])
        : "r"(a[0]), "r"(a[1]), "r"(a[2]), "r"(a[3]), "r"(b[0]), "r"(b[1]));
}

// ldmatrix x4 (LDSM in SASS)
#define LDSM4(r, addr) \
    asm volatile("ldmatrix.sync.aligned.m8n8.x4.shared.b16 {%0,%1,%2,%3}, [%4];" \
        : "=r"((r)[0]), "=r"((r)[1]), "=r"((r)[2]), "=r"((r)[3]) : "r"(addr))

__device__ __forceinline__ unsigned pack_h2(float x, float y) {
    __half2 h = __floats2half2_rn(x, y);
    return *reinterpret_cast<unsigned*>(&h);
}

// ---------------------------------------------------------------------------
// prep: weight images + zero degrees + convert x -> bf16, one kernel
// ---------------------------------------------------------------------------
__global__ void __launch_bounds__(256) prep_kernel(
    const float* __restrict__ wl1, const float* __restrict__ wr1,
    const float* __restrict__ wl2, const float* __restrict__ wr2,
    const float* __restrict__ w_out, const float* __restrict__ x, int n)
{
    int idx = blockIdx.x * 256 + threadIdx.x;
    const int NT = 2048 * 256;
    for (int j = idx; j < 2 * NMAX; j += NT) g_deg[j] = 0;
    for (int i = idx; i < n * 32; i += NT) {
        float4 v = __ldg(reinterpret_cast<const float4*>(x) + i);
        __nv_bfloat162 a = __floats2bfloat162_rn(v.x, v.y);
        __nv_bfloat162 b = __floats2bfloat162_rn(v.z, v.w);
        reinterpret_cast<uint2*>(g_xb)[i] =
            make_uint2(*reinterpret_cast<unsigned*>(&a), *reinterpret_cast<unsigned*>(&b));
    }
    if (idx < 65536) {
        int layer = idx >> 15;
        int rem   = idx & 32767;
        int c     = rem >> 14;
        int nrow  = (rem >> 7) & 127;
        int k     = rem & 127;
        const float* w = layer ? (c ? wr2 : wl2) : (c ? wr1 : wl1);
        float v = __ldg(w + k * 128 + nrow);
        g_wth[(layer * 2 + c) * 16384 + nrow * 128 + k] =
            __half_as_ushort(__float2half_rn(v));
    } else if (idx < 75776) {
        int j = idx - 65536;
        int nn = j >> 8;
        int k  = j & 255;
        float v = __ldg(w_out + k * 40 + nn);
        __half hb = __float2half_rn(v);
        __half lb = __float2half_rn(v - __half2float(hb));
        g_woth[nn * 256 + k] = __half_as_ushort(hb);
        g_wotl[nn * 256 + k] = __half_as_ushort(lb);
    }
}

// ---------------------------------------------------------------------------
// Merged CSR build for both edge lists
// ---------------------------------------------------------------------------
__global__ void __launch_bounds__(256) count_both_kernel(
    const int* __restrict__ ei1, const int* __restrict__ ei2, int E1, int E2)
{
    int e = blockIdx.x * 256 + threadIdx.x;
    if (e < E1) atomicAdd(&g_deg[__ldg(ei1 + E1 + e)], 1);
    int e2 = e - E1;
    if (e2 >= 0 && e2 < E2) atomicAdd(&g_deg[NMAX + __ldg(ei2 + E2 + e2)], 1);
}

__global__ void __launch_bounds__(1024) scan1_kernel(int n) {
    __shared__ int s[1024];
    int a = blockIdx.y;
    int t = threadIdx.x;
    int i = blockIdx.x * 1024 + t;
    int v = (i < n) ? g_deg[a * NMAX + i] : 0;
    s[t] = v;
    __syncthreads();
#pragma unroll
    for (int d = 1; d < 1024; d <<= 1) {
        int add = (t >= d) ? s[t - d] : 0;
        __syncthreads();
        s[t] += add;
        __syncthreads();
    }
    if (i < n) g_off[a * NMAX + i] = s[t] - v;
    if (t == 1023) g_aux[a * 512 + blockIdx.x] = s[1023];
}

// fused scan2+scan3
__global__ void __launch_bounds__(256) scan23_kernel(int n, int nb) {
    __shared__ int s[128];
    int a = blockIdx.y;
    int i = blockIdx.x * 256 + threadIdx.x;
    int c = blockIdx.x >> 2;
    if (threadIdx.x < nb) s[threadIdx.x] = g_aux[a * 512 + threadIdx.x];
    __syncthreads();
    int pre = 0;
    for (int j = 0; j < c; j++) pre += s[j];
    if (i < n) {
        int o = g_off[a * NMAX + i] + pre;
        g_off[a * NMAX + i] = o;
        g_cursor[a * NMAX + i] = o;
    }
}

__global__ void __launch_bounds__(256) fill_both_kernel(
    const int* __restrict__ ei1, const int* __restrict__ ei2, int E1, int E2)
{
    int e = blockIdx.x * 256 + threadIdx.x;
    if (e < E1) {
        int s = __ldg(ei1 + e);
        int d = __ldg(ei1 + E1 + e);
        int pos = atomicAdd(&g_cursor[d], 1);
        g_nbr[pos] = s;
    }
    int e2 = e - E1;
    if (e2 >= 0 && e2 < E2) {
        int s = __ldg(ei2 + e2);
        int d = __ldg(ei2 + E2 + e2);
        int pos = atomicAdd(&g_cursor[NMAX + d], 1);
        g_nbr[EMAX + pos] = s;
    }
}

// ---------------------------------------------------------------------------
// Gather-mean bf16: fp32 accumulate
// ---------------------------------------------------------------------------
__device__ __forceinline__ void add_bf16x4(float4& acc, uint2 p) {
    float2 a = __bfloat1622float2(*reinterpret_cast<__nv_bfloat162*>(&p.x));
    float2 b = __bfloat1622float2(*reinterpret_cast<__nv_bfloat162*>(&p.y));
    acc.x += a.x; acc.y += a.y; acc.z += b.x; acc.w += b.y;
}

__global__ void __launch_bounds__(256) gather_b16_kernel(
    const unsigned short* __restrict__ featb, int n, int csr)
{
    int v = (blockIdx.x * 256 + threadIdx.x) >> 5;
    int lane = threadIdx.x & 31;
    if (v >= n) return;
    int start = __ldg(g_off + csr * NMAX + v);
    int deg   = __ldg(g_deg + csr * NMAX + v);
    const int* nbr = g_nbr + csr * EMAX;
    const uint2* f = reinterpret_cast<const uint2*>(featb);
    float4 acc = make_float4(0.f, 0.f, 0.f, 0.f);
    int i = 0;
    for (; i + 4 <= deg; i += 4) {
        int s0 = __ldg(nbr + start + i);
        int s1 = __ldg(nbr + start + i + 1);
        int s2 = __ldg(nbr + start + i + 2);
        int s3 = __ldg(nbr + start + i + 3);
        uint2 p0 = __ldg(f + (size_t)s0 * 32 + lane);
        uint2 p1 = __ldg(f + (size_t)s1 * 32 + lane);
        uint2 p2 = __ldg(f + (size_t)s2 * 32 + lane);
        uint2 p3 = __ldg(f + (size_t)s3 * 32 + lane);
        add_bf16x4(acc, p0); add_bf16x4(acc, p1);
        add_bf16x4(acc, p2); add_bf16x4(acc, p3);
    }
    for (; i < deg; i++) {
        int s0 = __ldg(nbr + start + i);
        uint2 p0 = __ldg(f + (size_t)s0 * 32 + lane);
        add_bf16x4(acc, p0);
    }
    float inv = 1.0f / (float)max(deg, 1);
    acc.x *= inv; acc.y *= inv; acc.z *= inv; acc.w *= inv;
    reinterpret_cast<float4*>(g_agg)[(size_t)v * 32 + lane] = acc;
}

// ---------------------------------------------------------------------------
// HMMA SAGE layer: fp16 1-product main GEMM (A and W both fp16-rounded).
// MODE 0: out = g_h1 (fp32) + g_h1b (bf16 copy).  relu(agg@wl + xin@wr + b)
// MODE 1: layer-2 + fused head (fp16 2-product, W exact) -> d_out [n,40].
// ---------------------------------------------------------------------------
template <int MODE>
__global__ void __launch_bounds__(256) layer_mma_kernel(
    const float* __restrict__ xin, const float* __restrict__ bias,
    float* __restrict__ out, int n,
    const unsigned short* __restrict__ wth_base,
    const float* __restrict__ b_out)
{
    extern __shared__ unsigned short sm[];
    unsigned short* s_a  = sm;                       // 64 x APAD (fp16)
    unsigned short* s_wh = sm + 64 * APAD;           // 128 x APAD

    int tid = threadIdx.x, wid = tid >> 5, lane = tid & 31;
    int r0 = blockIdx.x * 64;
    int mrow = (wid & 1) * 32;
    int ncol = (wid >> 1) * 32;
    int rq = lane >> 2;

    unsigned base_a  = (unsigned)__cvta_generic_to_shared(s_a);
    unsigned base_wh = (unsigned)__cvta_generic_to_shared(s_wh);

    int arow = mrow + (lane & 7) + ((lane >> 3) & 1) * 8;
    int akk  = (lane >> 4) * 8;
    unsigned aOffA = (unsigned)((arow * APAD + akk) * 2);
    unsigned aOffB = (unsigned)(((arow + 16) * APAD + akk) * 2);

    int bn  = ncol + ((lane >> 4) & 1) * 8 + (lane & 7);
    int bkk = ((lane >> 3) & 1) * 8;
    unsigned bOff0 = (unsigned)((bn * APAD + bkk) * 2);
    unsigned bOff1 = (unsigned)(((bn + 16) * APAD + bkk) * 2);

    float acc[2][4][4];
#pragma unroll
    for (int mt = 0; mt < 2; mt++)
#pragma unroll
        for (int nt = 0; nt < 4; nt++)
#pragma unroll
            for (int q = 0; q < 4; q++) acc[mt][nt][q] = 0.f;

    for (int chunk = 0; chunk < 2; chunk++) {
        if (chunk) __syncthreads();   // protect smem reuse

        // ---- stage A (64 rows), fp32 -> fp16 ----
        const float4* src = (chunk == 0) ? reinterpret_cast<const float4*>(g_agg)
                                         : reinterpret_cast<const float4*>(xin);
#pragma unroll
        for (int i = 0; i < 8; i++) {
            int f = tid + i * 256;          // 64 rows * 32 float4
            int row = f >> 5, k4 = f & 31;
            int gr = r0 + row;
            if (gr >= n) gr = n - 1;
            float4 v = __ldg(src + (size_t)gr * 32 + k4);
            int o = row * APAD + k4 * 4;
            *reinterpret_cast<uint2*>(s_a + o) =
                make_uint2(pack_h2(v.x, v.y), pack_h2(v.z, v.w));
        }

        // ---- stage W chunk (fp16 image) ----
        {
            const uint2* gh = reinterpret_cast<const uint2*>(wth_base) + chunk * 4096;
#pragma unroll
            for (int i = 0; i < 16; i++) {
                int j = tid + i * 256;        // 128 rows * 32 uint2
                int nrow = j >> 5, kk = (j & 31) * 4;
                *reinterpret_cast<uint2*>(s_wh + nrow * APAD + kk) = __ldg(gh + j);
            }
        }
        __syncthreads();

        // ---- compute: 8 k-steps of m16n8k16, 1 product, LDSM staging ----
#pragma unroll
        for (int s = 0; s < 8; s++) {
            unsigned off = (unsigned)(s * 32);
            unsigned bh0[4], bh1[4];
            LDSM4(bh0, base_wh + bOff0 + off);
            LDSM4(bh1, base_wh + bOff1 + off);
#pragma unroll
            for (int mt = 0; mt < 2; mt++) {
                unsigned a[4];
                LDSM4(a, base_a + (mt ? aOffB : aOffA) + off);
                mma16816h(acc[mt][0], a, bh0 + 0);
                mma16816h(acc[mt][1], a, bh0 + 2);
                mma16816h(acc[mt][2], a, bh1 + 0);
                mma16816h(acc[mt][3], a, bh1 + 2);
            }
        }
    }

    if (MODE == 0) {
        // ---- epilogue: bias + relu -> g_h1 (fp32) + g_h1b (bf16) ----
#pragma unroll
        for (int mt = 0; mt < 2; mt++) {
#pragma unroll
            for (int nt = 0; nt < 4; nt++) {
                int col = ncol + nt * 8 + (lane & 3) * 2;
                float bx = __ldg(bias + col), by = __ldg(bias + col + 1);
#pragma unroll
                for (int q2 = 0; q2 < 2; q2++) {
                    int row = r0 + mrow + mt * 16 + rq + q2 * 8;
                    if (row < n) {
                        float vx = fmaxf(acc[mt][nt][q2 * 2 + 0] + bx, 0.f);
                        float vy = fmaxf(acc[mt][nt][q2 * 2 + 1] + by, 0.f);
                        *reinterpret_cast<float2*>(out + (size_t)row * 128 + col)
                            = make_float2(vx, vy);
                        __nv_bfloat162 bb = __floats2bfloat162_rn(vx, vy);
                        *reinterpret_cast<unsigned*>(g_h1b + (size_t)row * 128 + col)
                            = *reinterpret_cast<unsigned*>(&bb);
                    }
                }
            }
        }
        return;
    }

    // ================= MODE 1: fused head (fp16, 2-product exact-W) ========
    __syncthreads();   // everyone done reading main-phase smem

    unsigned short* s_hh = sm;                       // 64 x HPAD (fp16 cat-tile)
    unsigned short* s_oh = sm + 64 * HPAD;           // 40 x HPAD
    unsigned short* s_ol = s_oh + 40 * HPAD;

    // 1) store relu(h2)+bias fragments into cat-tile cols [128..256)
#pragma unroll
    for (int mt = 0; mt < 2; mt++) {
#pragma unroll
        for (int nt = 0; nt < 4; nt++) {
            int col = ncol + nt * 8 + (lane & 3) * 2;
            float bx = __ldg(bias + col), by = __ldg(bias + col + 1);
#pragma unroll
            for (int q2 = 0; q2 < 2; q2++) {
                int row = mrow + mt * 16 + rq + q2 * 8;
                float vx = fmaxf(acc[mt][nt][q2 * 2 + 0] + bx, 0.f);
                float vy = fmaxf(acc[mt][nt][q2 * 2 + 1] + by, 0.f);
                *reinterpret_cast<unsigned*>(s_hh + row * HPAD + 128 + col)
                    = pack_h2(vx, vy);
            }
        }
    }

    // 2) load h1 rows (fp32) into cat-tile cols [0..128) as fp16
    {
        const float4* h14 = reinterpret_cast<const float4*>(xin);  // xin == g_h1
#pragma unroll
        for (int i = 0; i < 8; i++) {
            int f = tid + i * 256;
            int row = f >> 5, k4 = f & 31;
            int gr = r0 + row;
            if (gr >= n) gr = n - 1;
            float4 v = __ldg(h14 + (size_t)gr * 32 + k4);
            int o = row * HPAD + k4 * 4;
            *reinterpret_cast<uint2*>(s_hh + o) =
                make_uint2(pack_h2(v.x, v.y), pack_h2(v.z, v.w));
        }
    }

    // 3) stage w_out images [40 x 256] fp16 hi/lo
    {
        const uint2* gh = reinterpret_cast<const uint2*>(g_woth);
        const uint2* gl = reinterpret_cast<const uint2*>(g_wotl);
#pragma unroll
        for (int i = 0; i < 10; i++) {
            int j = tid + i * 256;            // 40*64 = 2560
            if (j < 2560) {
                int nn = j >> 6, kk = (j & 63) * 4;
                int o = nn * HPAD + kk;
                *reinterpret_cast<uint2*>(s_oh + o) = __ldg(gh + j);
                *reinterpret_cast<uint2*>(s_ol + o) = __ldg(gl + j);
            }
        }
    }
    __syncthreads();

    // 4) head GEMM
    int wg = wid >> 1;
    int mrow2 = (wid & 1) * 32;
    int nts0 = wg, nts1 = 4;
    int nnt = (wg == 0) ? 2 : 1;
    int kc_h = (lane & 3) * 2;

    float acc2[2][2][4];
#pragma unroll
    for (int mt = 0; mt < 2; mt++)
#pragma unroll
        for (int t = 0; t < 2; t++)
#pragma unroll
            for (int q = 0; q < 4; q++) acc2[mt][t][q] = 0.f;

#pragma unroll
    for (int s = 0; s < 16; s++) {
        int kc = s * 16 + kc_h;
        unsigned bh[2][2], bl[2][2];
        for (int t = 0; t < nnt; t++) {
            int nt = t ? nts1 : nts0;
            int nn = nt * 8 + rq;
            bh[t][0] = *reinterpret_cast<unsigned*>(s_oh + nn * HPAD + kc);
            bh[t][1] = *reinterpret_cast<unsigned*>(s_oh + nn * HPAD + kc + 8);
            bl[t][0] = *reinterpret_cast<unsigned*>(s_ol + nn * HPAD + kc);
            bl[t][1] = *reinterpret_cast<unsigned*>(s_ol + nn * HPAD + kc + 8);
        }
#pragma unroll
        for (int mt = 0; mt < 2; mt++) {
            int rr = mrow2 + mt * 16 + rq;
            unsigned ah[4];
            ah[0] = *reinterpret_cast<unsigned*>(s_hh + rr * HPAD + kc);
            ah[1] = *reinterpret_cast<unsigned*>(s_hh + (rr + 8) * HPAD + kc);
            ah[2] = *reinterpret_cast<unsigned*>(s_hh + rr * HPAD + kc + 8);
            ah[3] = *reinterpret_cast<unsigned*>(s_hh + (rr + 8) * HPAD + kc + 8);
            for (int t = 0; t < nnt; t++) {
                mma16816h(acc2[mt][t], ah, bh[t]);
                mma16816h(acc2[mt][t], ah, bl[t]);
            }
        }
    }

    // 5) write d_out
#pragma unroll
    for (int mt = 0; mt < 2; mt++) {
        for (int t = 0; t < nnt; t++) {
            int nt = t ? nts1 : nts0;
            int col = nt * 8 + (lane & 3) * 2;
            float bx = __ldg(b_out + col), by = __ldg(b_out + col + 1);
#pragma unroll
            for (int q2 = 0; q2 < 2; q2++) {
                int row = r0 + mrow2 + mt * 16 + rq + q2 * 8;
                if (row < n) {
                    float2 o = make_float2(acc2[mt][t][q2 * 2 + 0] + bx,
                                           acc2[mt][t][q2 * 2 + 1] + by);
                    *reinterpret_cast<float2*>(out + (size_t)row * 40 + col) = o;
                }
            }
        }
    }
}

// ---------------------------------------------------------------------------
extern "C" void kernel_launch(void* const* d_in, const int* in_sizes, int n_in,
                              void* d_out, int out_size)
{
    const float* x     = (const float*)d_in[0];
    const int*   ei1   = (const int*)d_in[1];
    const int*   ei2   = (const int*)d_in[2];
    const float* wl1   = (const float*)d_in[3];
    const float* wr1   = (const float*)d_in[4];
    const float* b1    = (const float*)d_in[5];
    const float* wl2   = (const float*)d_in[6];
    const float* wr2   = (const float*)d_in[7];
    const float* b2    = (const float*)d_in[8];
    const float* w_out = (const float*)d_in[9];
    const float* b_out = (const float*)d_in[10];

    int n  = in_sizes[0] / D;
    int E1 = in_sizes[1] / 2;
    int E2 = in_sizes[2] / 2;

    void *p_h1 = nullptr, *p_wth = nullptr, *p_xb = nullptr, *p_h1b = nullptr;
    cudaGetSymbolAddress(&p_h1, g_h1);
    cudaGetSymbolAddress(&p_wth, g_wth);
    cudaGetSymbolAddress(&p_xb, g_xb);
    cudaGetSymbolAddress(&p_h1b, g_h1b);
    float* h1 = (float*)p_h1;
    const unsigned short* wth = (const unsigned short*)p_wth;
    const unsigned short* xb  = (const unsigned short*)p_xb;
    const unsigned short* h1b = (const unsigned short*)p_h1b;

    // max(main phase 52224, head phase 76032)
    const int LAYER_SMEM = 64 * HPAD * 2 + 2 * 40 * HPAD * 2;  // 76032 B
    cudaFuncSetAttribute(layer_mma_kernel<0>,
                         cudaFuncAttributeMaxDynamicSharedMemorySize, LAYER_SMEM);
    cudaFuncSetAttribute(layer_mma_kernel<1>,
                         cudaFuncAttributeMaxDynamicSharedMemorySize, LAYER_SMEM);

    int nb_scan = (n + 1023) / 1024;
    int layer_blocks = (n + 63) / 64;
    int gather_blocks = (n * 32 + 255) / 256;

    // ---- prep (zero degs + weight images + convert x) ----
    prep_kernel<<<2048, 256>>>(wl1, wr1, wl2, wr2, w_out, x, n);

    // ---- batched CSR build for both edge lists ----
    count_both_kernel<<<(E1 + E2 + 255) / 256, 256>>>(ei1, ei2, E1, E2);
    scan1_kernel<<<dim3(nb_scan, 2), 1024>>>(n);
    scan23_kernel<<<dim3((n + 255) / 256, 2), 256>>>(n, nb_scan);
    fill_both_kernel<<<(E1 + E2 + 255) / 256, 256>>>(ei1, ei2, E1, E2);

    // ---- layer 1 ----
    gather_b16_kernel<<<gather_blocks, 256>>>(xb, n, 0);
    layer_mma_kernel<0><<<layer_blocks, 256, LAYER_SMEM>>>(
        x, b1, h1, n, wth, b_out);

    // ---- layer 2 + fused head ----
    gather_b16_kernel<<<gather_blocks, 256>>>(h1b, n, 1);
    layer_mma_kernel<1><<<layer_blocks, 256, LAYER_SMEM>>>(
        h1, b2, (float*)d_out, n, wth + 32768, b_out);
}

// round 15
// speedup vs baseline: 1.5000x; 1.1195x over previous
#include <cuda_runtime.h>
#include <cuda_fp16.h>
#include <cstddef>
#include <cstdint>

#define NMAX 100000
#define EMAX 1700000
#define D 128
#define APAD 136   // padded fp16 row stride (main GEMM); 68 words % 32 == 4 -> LDSM conflict-free
#define HPAD 264   // padded fp16 row stride (head phase, K=256)

// ---------------------------------------------------------------------------
// Scratch (device-global, allocation-free per harness rules). All features fp16.
// ---------------------------------------------------------------------------
__device__ unsigned short g_aggh[(size_t)NMAX * D];  // gather output
__device__ unsigned short g_h1h[(size_t)NMAX * D];   // layer-1 output
__device__ unsigned short g_xh[(size_t)NMAX * D];    // fp16 copy of x
__device__ int   g_deg[2 * NMAX];
__device__ int   g_off[2 * NMAX];
__device__ int   g_cursor[2 * NMAX];
__device__ int   g_nbr[2 * EMAX];
__device__ int   g_aux[1024];
// fp16 layer weight images (single, rounded): [layer][chunk][n_outcol][k]
__device__ unsigned short g_wth[4 * 128 * 128];
// fp16 hi/lo head weight images (exact 2-term): [n_outcol(40)][k(256)]
__device__ unsigned short g_woth[40 * 256];
__device__ unsigned short g_wotl[40 * 256];

// mma.sync m16n8k16 fp16 inputs, fp32 accum (plain-target PTX; HMMA in SASS)
__device__ __forceinline__ void mma16816h(float* c, const unsigned* a, const unsigned* b) {
    asm volatile(
        "mma.sync.aligned.m16n8k16.row.col.f32.f16.f16.f32 "
        "{%0,%1,%2,%3}, {%4,%5,%6,%7}, {%8,%9}, {%0,%1,%2,%3};"
        : "+f"(c[0]), "+f"(c[1]), "+f"(c[2]), "+f"(c[3])
        : "r"(a[0]), "r"(a[1]), "r"(a[2]), "r"(a[3]), "r"(b[0]), "r"(b[1]));
}

// ldmatrix x4 (LDSM in SASS)
#define LDSM4(r, addr) \
    asm volatile("ldmatrix.sync.aligned.m8n8.x4.shared.b16 {%0,%1,%2,%3}, [%4];" \
        : "=r"((r)[0]), "=r"((r)[1]), "=r"((r)[2]), "=r"((r)[3]) : "r"(addr))

__device__ __forceinline__ unsigned pack_h2(float x, float y) {
    __half2 h = __floats2half2_rn(x, y);
    return *reinterpret_cast<unsigned*>(&h);
}

// ---------------------------------------------------------------------------
// prep: weight images + zero degrees + convert x -> fp16, one kernel
// ---------------------------------------------------------------------------
__global__ void __launch_bounds__(256) prep_kernel(
    const float* __restrict__ wl1, const float* __restrict__ wr1,
    const float* __restrict__ wl2, const float* __restrict__ wr2,
    const float* __restrict__ w_out, const float* __restrict__ x, int n)
{
    int idx = blockIdx.x * 256 + threadIdx.x;
    const int NT = 2048 * 256;
    for (int j = idx; j < 2 * NMAX; j += NT) g_deg[j] = 0;
    for (int i = idx; i < n * 32; i += NT) {
        float4 v = __ldg(reinterpret_cast<const float4*>(x) + i);
        reinterpret_cast<uint2*>(g_xh)[i] =
            make_uint2(pack_h2(v.x, v.y), pack_h2(v.z, v.w));
    }
    if (idx < 65536) {
        int layer = idx >> 15;
        int rem   = idx & 32767;
        int c     = rem >> 14;
        int nrow  = (rem >> 7) & 127;
        int k     = rem & 127;
        const float* w = layer ? (c ? wr2 : wl2) : (c ? wr1 : wl1);
        float v = __ldg(w + k * 128 + nrow);
        g_wth[(layer * 2 + c) * 16384 + nrow * 128 + k] =
            __half_as_ushort(__float2half_rn(v));
    } else if (idx < 75776) {
        int j = idx - 65536;
        int nn = j >> 8;
        int k  = j & 255;
        float v = __ldg(w_out + k * 40 + nn);
        __half hb = __float2half_rn(v);
        __half lb = __float2half_rn(v - __half2float(hb));
        g_woth[nn * 256 + k] = __half_as_ushort(hb);
        g_wotl[nn * 256 + k] = __half_as_ushort(lb);
    }
}

// ---------------------------------------------------------------------------
// Merged CSR build for both edge lists
// ---------------------------------------------------------------------------
__global__ void __launch_bounds__(256) count_both_kernel(
    const int* __restrict__ ei1, const int* __restrict__ ei2, int E1, int E2)
{
    int e = blockIdx.x * 256 + threadIdx.x;
    if (e < E1) atomicAdd(&g_deg[__ldg(ei1 + E1 + e)], 1);
    int e2 = e - E1;
    if (e2 >= 0 && e2 < E2) atomicAdd(&g_deg[NMAX + __ldg(ei2 + E2 + e2)], 1);
}

__global__ void __launch_bounds__(1024) scan1_kernel(int n) {
    __shared__ int s[1024];
    int a = blockIdx.y;
    int t = threadIdx.x;
    int i = blockIdx.x * 1024 + t;
    int v = (i < n) ? g_deg[a * NMAX + i] : 0;
    s[t] = v;
    __syncthreads();
#pragma unroll
    for (int d = 1; d < 1024; d <<= 1) {
        int add = (t >= d) ? s[t - d] : 0;
        __syncthreads();
        s[t] += add;
        __syncthreads();
    }
    if (i < n) g_off[a * NMAX + i] = s[t] - v;
    if (t == 1023) g_aux[a * 512 + blockIdx.x] = s[1023];
}

// fused scan2+scan3
__global__ void __launch_bounds__(256) scan23_kernel(int n, int nb) {
    __shared__ int s[128];
    int a = blockIdx.y;
    int i = blockIdx.x * 256 + threadIdx.x;
    int c = blockIdx.x >> 2;
    if (threadIdx.x < nb) s[threadIdx.x] = g_aux[a * 512 + threadIdx.x];
    __syncthreads();
    int pre = 0;
    for (int j = 0; j < c; j++) pre += s[j];
    if (i < n) {
        int o = g_off[a * NMAX + i] + pre;
        g_off[a * NMAX + i] = o;
        g_cursor[a * NMAX + i] = o;
    }
}

__global__ void __launch_bounds__(256) fill_both_kernel(
    const int* __restrict__ ei1, const int* __restrict__ ei2, int E1, int E2)
{
    int e = blockIdx.x * 256 + threadIdx.x;
    if (e < E1) {
        int s = __ldg(ei1 + e);
        int d = __ldg(ei1 + E1 + e);
        int pos = atomicAdd(&g_cursor[d], 1);
        g_nbr[pos] = s;
    }
    int e2 = e - E1;
    if (e2 >= 0 && e2 < E2) {
        int s = __ldg(ei2 + e2);
        int d = __ldg(ei2 + E2 + e2);
        int pos = atomicAdd(&g_cursor[NMAX + d], 1);
        g_nbr[EMAX + pos] = s;
    }
}

// ---------------------------------------------------------------------------
// Gather-mean fp16 in / fp16 out, fp32 accumulate
// ---------------------------------------------------------------------------
__device__ __forceinline__ void add_f16x4(float4& acc, uint2 p) {
    float2 a = __half22float2(*reinterpret_cast<__half2*>(&p.x));
    float2 b = __half22float2(*reinterpret_cast<__half2*>(&p.y));
    acc.x += a.x; acc.y += a.y; acc.z += b.x; acc.w += b.y;
}

__global__ void __launch_bounds__(256) gather_h16_kernel(
    const unsigned short* __restrict__ feath, int n, int csr)
{
    int v = (blockIdx.x * 256 + threadIdx.x) >> 5;
    int lane = threadIdx.x & 31;
    if (v >= n) return;
    int start = __ldg(g_off + csr * NMAX + v);
    int deg   = __ldg(g_deg + csr * NMAX + v);
    const int* nbr = g_nbr + csr * EMAX;
    const uint2* f = reinterpret_cast<const uint2*>(feath);
    float4 acc = make_float4(0.f, 0.f, 0.f, 0.f);
    int i = 0;
    for (; i + 4 <= deg; i += 4) {
        int s0 = __ldg(nbr + start + i);
        int s1 = __ldg(nbr + start + i + 1);
        int s2 = __ldg(nbr + start + i + 2);
        int s3 = __ldg(nbr + start + i + 3);
        uint2 p0 = __ldg(f + (size_t)s0 * 32 + lane);
        uint2 p1 = __ldg(f + (size_t)s1 * 32 + lane);
        uint2 p2 = __ldg(f + (size_t)s2 * 32 + lane);
        uint2 p3 = __ldg(f + (size_t)s3 * 32 + lane);
        add_f16x4(acc, p0); add_f16x4(acc, p1);
        add_f16x4(acc, p2); add_f16x4(acc, p3);
    }
    for (; i < deg; i++) {
        int s0 = __ldg(nbr + start + i);
        uint2 p0 = __ldg(f + (size_t)s0 * 32 + lane);
        add_f16x4(acc, p0);
    }
    float inv = 1.0f / (float)max(deg, 1);
    reinterpret_cast<uint2*>(g_aggh)[(size_t)v * 32 + lane] =
        make_uint2(pack_h2(acc.x * inv, acc.y * inv),
                   pack_h2(acc.z * inv, acc.w * inv));
}

// ---------------------------------------------------------------------------
// HMMA SAGE layer: 128-row tile, 512 threads (16 warps = 8M x 2N, warp 16x64).
// fp16 1-product main GEMM; all A sources fp16 (raw copy into smem).
// MODE 0: out -> g_h1h (fp16).  relu(agg@wl + xin@wr + b)
// MODE 1: layer-2 + fused head (fp16 2-product exact-W) -> d_out [n,40].
// ---------------------------------------------------------------------------
template <int MODE>
__global__ void __launch_bounds__(512) layer_mma_kernel(
    const unsigned short* __restrict__ xin_h, const float* __restrict__ bias,
    float* __restrict__ out, int n,
    const unsigned short* __restrict__ wth_base,
    const float* __restrict__ b_out)
{
    extern __shared__ unsigned short sm[];
    unsigned short* s_a  = sm;                       // 128 x APAD (fp16)
    unsigned short* s_wh = sm + 128 * APAD;          // 128 x APAD

    int tid = threadIdx.x, wid = tid >> 5, lane = tid & 31;
    int r0 = blockIdx.x * 128;
    int mrow = (wid & 7) * 16;    // warp M origin (16 rows)
    int ncol = (wid >> 3) * 64;   // warp N origin (64 cols)
    int rq = lane >> 2;

    unsigned base_a  = (unsigned)__cvta_generic_to_shared(s_a);
    unsigned base_wh = (unsigned)__cvta_generic_to_shared(s_wh);

    int arow = mrow + (lane & 7) + ((lane >> 3) & 1) * 8;
    int akk  = (lane >> 4) * 8;
    unsigned aOff = (unsigned)((arow * APAD + akk) * 2);

    int bn  = ncol + ((lane >> 4) & 1) * 8 + (lane & 7);
    int bkk = ((lane >> 3) & 1) * 8;
    unsigned bOff[4];
#pragma unroll
    for (int p = 0; p < 4; p++)
        bOff[p] = (unsigned)(((bn + p * 16) * APAD + bkk) * 2);

    float acc[8][4];
#pragma unroll
    for (int nt = 0; nt < 8; nt++)
#pragma unroll
        for (int q = 0; q < 4; q++) acc[nt][q] = 0.f;

    for (int chunk = 0; chunk < 2; chunk++) {
        if (chunk) __syncthreads();   // protect smem reuse

        // ---- stage A (128 rows fp16, raw uint2 copy) ----
        const uint2* src = reinterpret_cast<const uint2*>(
            chunk == 0 ? g_aggh : xin_h);
#pragma unroll
        for (int i = 0; i < 8; i++) {
            int j = tid + i * 512;          // 128 rows * 32 uint2
            int row = j >> 5, k4 = j & 31;
            int gr = r0 + row;
            if (gr >= n) gr = n - 1;
            *reinterpret_cast<uint2*>(s_a + row * APAD + k4 * 4) =
                __ldg(src + (size_t)gr * 32 + k4);
        }

        // ---- stage W chunk (fp16 image) ----
        {
            const uint2* gh = reinterpret_cast<const uint2*>(wth_base) + chunk * 4096;
#pragma unroll
            for (int i = 0; i < 8; i++) {
                int j = tid + i * 512;        // 128 rows * 32 uint2
                int nrow = j >> 5, kk = (j & 31) * 4;
                *reinterpret_cast<uint2*>(s_wh + nrow * APAD + kk) = __ldg(gh + j);
            }
        }
        __syncthreads();

        // ---- compute: 8 k-steps of m16n8k16, 1 product, LDSM staging ----
#pragma unroll
        for (int s = 0; s < 8; s++) {
            unsigned off = (unsigned)(s * 32);
            unsigned a[4];
            LDSM4(a, base_a + aOff + off);
#pragma unroll
            for (int p = 0; p < 4; p++) {
                unsigned bh[4];
                LDSM4(bh, base_wh + bOff[p] + off);
                mma16816h(acc[p * 2 + 0], a, bh + 0);
                mma16816h(acc[p * 2 + 1], a, bh + 2);
            }
        }
    }

    if (MODE == 0) {
        // ---- epilogue: bias + relu -> g_h1h (fp16) ----
#pragma unroll
        for (int nt = 0; nt < 8; nt++) {
            int col = ncol + nt * 8 + (lane & 3) * 2;
            float bx = __ldg(bias + col), by = __ldg(bias + col + 1);
#pragma unroll
            for (int q2 = 0; q2 < 2; q2++) {
                int row = r0 + mrow + rq + q2 * 8;
                if (row < n) {
                    float vx = fmaxf(acc[nt][q2 * 2 + 0] + bx, 0.f);
                    float vy = fmaxf(acc[nt][q2 * 2 + 1] + by, 0.f);
                    *reinterpret_cast<unsigned*>(g_h1h + (size_t)row * 128 + col)
                        = pack_h2(vx, vy);
                }
            }
        }
        return;
    }

    // ================= MODE 1: fused head (fp16, 2-product exact-W) ========
    __syncthreads();   // everyone done reading main-phase smem

    unsigned short* s_hh = sm;                       // 128 x HPAD (fp16 cat-tile)
    unsigned short* s_oh = sm + 128 * HPAD;          // 40 x HPAD
    unsigned short* s_ol = s_oh + 40 * HPAD;

    // 1) store relu(h2)+bias fragments into cat-tile cols [128..256)
#pragma unroll
    for (int nt = 0; nt < 8; nt++) {
        int col = ncol + nt * 8 + (lane & 3) * 2;
        float bx = __ldg(bias + col), by = __ldg(bias + col + 1);
#pragma unroll
        for (int q2 = 0; q2 < 2; q2++) {
            int row = mrow + rq + q2 * 8;
            float vx = fmaxf(acc[nt][q2 * 2 + 0] + bx, 0.f);
            float vy = fmaxf(acc[nt][q2 * 2 + 1] + by, 0.f);
            *reinterpret_cast<unsigned*>(s_hh + row * HPAD + 128 + col)
                = pack_h2(vx, vy);
        }
    }

    // 2) copy h1 rows (fp16) into cat-tile cols [0..128)
    {
        const uint2* h1s = reinterpret_cast<const uint2*>(xin_h);  // == g_h1h
#pragma unroll
        for (int i = 0; i < 8; i++) {
            int j = tid + i * 512;
            int row = j >> 5, k4 = j & 31;
            int gr = r0 + row;
            if (gr >= n) gr = n - 1;
            *reinterpret_cast<uint2*>(s_hh + row * HPAD + k4 * 4) =
                __ldg(h1s + (size_t)gr * 32 + k4);
        }
    }

    // 3) stage w_out images [40 x 256] fp16 hi/lo
    {
        const uint2* gh = reinterpret_cast<const uint2*>(g_woth);
        const uint2* gl = reinterpret_cast<const uint2*>(g_wotl);
#pragma unroll
        for (int i = 0; i < 5; i++) {
            int j = tid + i * 512;            // 40*64 = 2560
            if (j < 2560) {
                int nn = j >> 6, kk = (j & 63) * 4;
                int o = nn * HPAD + kk;
                *reinterpret_cast<uint2*>(s_oh + o) = __ldg(gh + j);
                *reinterpret_cast<uint2*>(s_ol + o) = __ldg(gl + j);
            }
        }
    }
    __syncthreads();

    // 4) head GEMM: M=128 (8 warps x 16 rows), N=40; warp group covers
    //    n-tiles {0,1,2} (grp 0) or {3,4} (grp 1)
    int ngrp = wid >> 3;
    int mrow2 = (wid & 7) * 16;
    int nnt = ngrp ? 2 : 3;
    int ntbase = ngrp ? 3 : 0;
    int kc_h = (lane & 3) * 2;

    float acc2[3][4];
#pragma unroll
    for (int t = 0; t < 3; t++)
#pragma unroll
        for (int q = 0; q < 4; q++) acc2[t][q] = 0.f;

#pragma unroll
    for (int s = 0; s < 16; s++) {
        int kc = s * 16 + kc_h;
        unsigned ah[4];
        ah[0] = *reinterpret_cast<unsigned*>(s_hh + (mrow2 + rq) * HPAD + kc);
        ah[1] = *reinterpret_cast<unsigned*>(s_hh + (mrow2 + rq + 8) * HPAD + kc);
        ah[2] = *reinterpret_cast<unsigned*>(s_hh + (mrow2 + rq) * HPAD + kc + 8);
        ah[3] = *reinterpret_cast<unsigned*>(s_hh + (mrow2 + rq + 8) * HPAD + kc + 8);
        for (int t = 0; t < nnt; t++) {
            int nn = (ntbase + t) * 8 + rq;
            unsigned bh[2], bl[2];
            bh[0] = *reinterpret_cast<unsigned*>(s_oh + nn * HPAD + kc);
            bh[1] = *reinterpret_cast<unsigned*>(s_oh + nn * HPAD + kc + 8);
            bl[0] = *reinterpret_cast<unsigned*>(s_ol + nn * HPAD + kc);
            bl[1] = *reinterpret_cast<unsigned*>(s_ol + nn * HPAD + kc + 8);
            mma16816h(acc2[t], ah, bh);
            mma16816h(acc2[t], ah, bl);
        }
    }

    // 5) write d_out
    for (int t = 0; t < nnt; t++) {
        int col = (ntbase + t) * 8 + (lane & 3) * 2;
        float bx = __ldg(b_out + col), by = __ldg(b_out + col + 1);
#pragma unroll
        for (int q2 = 0; q2 < 2; q2++) {
            int row = r0 + mrow2 + rq + q2 * 8;
            if (row < n) {
                float2 o = make_float2(acc2[t][q2 * 2 + 0] + bx,
                                       acc2[t][q2 * 2 + 1] + by);
                *reinterpret_cast<float2*>(out + (size_t)row * 40 + col) = o;
            }
        }
    }
}

// ---------------------------------------------------------------------------
extern "C" void kernel_launch(void* const* d_in, const int* in_sizes, int n_in,
                              void* d_out, int out_size)
{
    const float* x     = (const float*)d_in[0];
    const int*   ei1   = (const int*)d_in[1];
    const int*   ei2   = (const int*)d_in[2];
    const float* wl1   = (const float*)d_in[3];
    const float* wr1   = (const float*)d_in[4];
    const float* b1    = (const float*)d_in[5];
    const float* wl2   = (const float*)d_in[6];
    const float* wr2   = (const float*)d_in[7];
    const float* b2    = (const float*)d_in[8];
    const float* w_out = (const float*)d_in[9];
    const float* b_out = (const float*)d_in[10];

    int n  = in_sizes[0] / D;
    int E1 = in_sizes[1] / 2;
    int E2 = in_sizes[2] / 2;

    void *p_wth = nullptr, *p_xh = nullptr, *p_h1h = nullptr;
    cudaGetSymbolAddress(&p_wth, g_wth);
    cudaGetSymbolAddress(&p_xh, g_xh);
    cudaGetSymbolAddress(&p_h1h, g_h1h);
    const unsigned short* wth = (const unsigned short*)p_wth;
    const unsigned short* xh  = (const unsigned short*)p_xh;
    const unsigned short* h1h = (const unsigned short*)p_h1h;

    // max(main phase 69632, head phase 109824)
    const int LAYER_SMEM = 128 * HPAD * 2 + 2 * 40 * HPAD * 2;  // 109824 B
    cudaFuncSetAttribute(layer_mma_kernel<0>,
                         cudaFuncAttributeMaxDynamicSharedMemorySize, LAYER_SMEM);
    cudaFuncSetAttribute(layer_mma_kernel<1>,
                         cudaFuncAttributeMaxDynamicSharedMemorySize, LAYER_SMEM);

    int nb_scan = (n + 1023) / 1024;
    int layer_blocks = (n + 127) / 128;
    int gather_blocks = (n * 32 + 255) / 256;

    // ---- prep (zero degs + weight images + convert x) ----
    prep_kernel<<<2048, 256>>>(wl1, wr1, wl2, wr2, w_out, x, n);

    // ---- batched CSR build for both edge lists ----
    count_both_kernel<<<(E1 + E2 + 255) / 256, 256>>>(ei1, ei2, E1, E2);
    scan1_kernel<<<dim3(nb_scan, 2), 1024>>>(n);
    scan23_kernel<<<dim3((n + 255) / 256, 2), 256>>>(n, nb_scan);
    fill_both_kernel<<<(E1 + E2 + 255) / 256, 256>>>(ei1, ei2, E1, E2);

    // ---- layer 1 ----
    gather_h16_kernel<<<gather_blocks, 256>>>(xh, n, 0);
    layer_mma_kernel<0><<<layer_blocks, 512, LAYER_SMEM>>>(
        xh, b1, nullptr, n, wth, b_out);

    // ---- layer 2 + fused head ----
    gather_h16_kernel<<<gather_blocks, 256>>>(h1h, n, 1);
    layer_mma_kernel<1><<<layer_blocks, 512, LAYER_SMEM>>>(
        h1h, b2, (float*)d_out, n, wth + 32768, b_out);
}

// round 16
// speedup vs baseline: 1.5398x; 1.0265x over previous
#include <cuda_runtime.h>
#include <cuda_fp16.h>
#include <cstddef>
#include <cstdint>

#define NMAX 100000
#define EMAX 1700000
#define D 128
#define APAD 136   // padded fp16 row stride (main GEMM); 68 words % 32 == 4 -> LDSM conflict-free
#define HPAD 264   // padded fp16 row stride (head phase, K=256)

// ---------------------------------------------------------------------------
// Scratch (device-global, allocation-free per harness rules). All features fp16.
// ---------------------------------------------------------------------------
__device__ unsigned short g_aggh[(size_t)NMAX * D];  // gather output
__device__ unsigned short g_h1h[(size_t)NMAX * D];   // layer-1 output
__device__ unsigned short g_xh[(size_t)NMAX * D];    // fp16 copy of x
__device__ int   g_deg[2 * NMAX];
__device__ int   g_off[2 * NMAX];
__device__ int   g_cursor[2 * NMAX];
__device__ int   g_nbr[2 * EMAX];
__device__ int   g_aux[1024];
// fp16 layer weight images (single, rounded): [layer][chunk][n_outcol][k]
__device__ unsigned short g_wth[4 * 128 * 128];
// fp16 hi/lo head weight images (exact 2-term): [n_outcol(40)][k(256)]
__device__ unsigned short g_woth[40 * 256];
__device__ unsigned short g_wotl[40 * 256];

// mma.sync m16n8k16 fp16 inputs, fp32 accum (plain-target PTX; HMMA in SASS)
__device__ __forceinline__ void mma16816h(float* c, const unsigned* a, const unsigned* b) {
    asm volatile(
        "mma.sync.aligned.m16n8k16.row.col.f32.f16.f16.f32 "
        "{%0,%1,%2,%3}, {%4,%5,%6,%7}, {%8,%9}, {%0,%1,%2,%3};"
        : "+f"(c[0]), "+f"(c[1]), "+f"(c[2]), "+f"(c[3])
        : "r"(a[0]), "r"(a[1]), "r"(a[2]), "r"(a[3]), "r"(b[0]), "r"(b[1]));
}

// ldmatrix x4 (LDSM in SASS)
#define LDSM4(r, addr) \
    asm volatile("ldmatrix.sync.aligned.m8n8.x4.shared.b16 {%0,%1,%2,%3}, [%4];" \
        : "=r"((r)[0]), "=r"((r)[1]), "=r"((r)[2]), "=r"((r)[3]) : "r"(addr))

__device__ __forceinline__ unsigned pack_h2(float x, float y) {
    __half2 h = __floats2half2_rn(x, y);
    return *reinterpret_cast<unsigned*>(&h);
}

// ---------------------------------------------------------------------------
// prep: weight images + zero degrees + convert x -> fp16, one kernel
// ---------------------------------------------------------------------------
__global__ void __launch_bounds__(256) prep_kernel(
    const float* __restrict__ wl1, const float* __restrict__ wr1,
    const float* __restrict__ wl2, const float* __restrict__ wr2,
    const float* __restrict__ w_out, const float* __restrict__ x, int n)
{
    int idx = blockIdx.x * 256 + threadIdx.x;
    const int NT = 2048 * 256;
    for (int j = idx; j < 2 * NMAX; j += NT) g_deg[j] = 0;
    for (int i = idx; i < n * 32; i += NT) {
        float4 v = __ldg(reinterpret_cast<const float4*>(x) + i);
        reinterpret_cast<uint2*>(g_xh)[i] =
            make_uint2(pack_h2(v.x, v.y), pack_h2(v.z, v.w));
    }
    if (idx < 65536) {
        int layer = idx >> 15;
        int rem   = idx & 32767;
        int c     = rem >> 14;
        int nrow  = (rem >> 7) & 127;
        int k     = rem & 127;
        const float* w = layer ? (c ? wr2 : wl2) : (c ? wr1 : wl1);
        float v = __ldg(w + k * 128 + nrow);
        g_wth[(layer * 2 + c) * 16384 + nrow * 128 + k] =
            __half_as_ushort(__float2half_rn(v));
    } else if (idx < 75776) {
        int j = idx - 65536;
        int nn = j >> 8;
        int k  = j & 255;
        float v = __ldg(w_out + k * 40 + nn);
        __half hb = __float2half_rn(v);
        __half lb = __float2half_rn(v - __half2float(hb));
        g_woth[nn * 256 + k] = __half_as_ushort(hb);
        g_wotl[nn * 256 + k] = __half_as_ushort(lb);
    }
}

// ---------------------------------------------------------------------------
// Merged CSR build for both edge lists
// ---------------------------------------------------------------------------
__global__ void __launch_bounds__(256) count_both_kernel(
    const int* __restrict__ ei1, const int* __restrict__ ei2, int E1, int E2)
{
    int e = blockIdx.x * 256 + threadIdx.x;
    if (e < E1) atomicAdd(&g_deg[__ldg(ei1 + E1 + e)], 1);
    int e2 = e - E1;
    if (e2 >= 0 && e2 < E2) atomicAdd(&g_deg[NMAX + __ldg(ei2 + E2 + e2)], 1);
}

__global__ void __launch_bounds__(1024) scan1_kernel(int n) {
    __shared__ int s[1024];
    int a = blockIdx.y;
    int t = threadIdx.x;
    int i = blockIdx.x * 1024 + t;
    int v = (i < n) ? g_deg[a * NMAX + i] : 0;
    s[t] = v;
    __syncthreads();
#pragma unroll
    for (int d = 1; d < 1024; d <<= 1) {
        int add = (t >= d) ? s[t - d] : 0;
        __syncthreads();
        s[t] += add;
        __syncthreads();
    }
    if (i < n) g_off[a * NMAX + i] = s[t] - v;
    if (t == 1023) g_aux[a * 512 + blockIdx.x] = s[1023];
}

// fused scan2+scan3
__global__ void __launch_bounds__(256) scan23_kernel(int n, int nb) {
    __shared__ int s[128];
    int a = blockIdx.y;
    int i = blockIdx.x * 256 + threadIdx.x;
    int c = blockIdx.x >> 2;
    if (threadIdx.x < nb) s[threadIdx.x] = g_aux[a * 512 + threadIdx.x];
    __syncthreads();
    int pre = 0;
    for (int j = 0; j < c; j++) pre += s[j];
    if (i < n) {
        int o = g_off[a * NMAX + i] + pre;
        g_off[a * NMAX + i] = o;
        g_cursor[a * NMAX + i] = o;
    }
}

__global__ void __launch_bounds__(256) fill_both_kernel(
    const int* __restrict__ ei1, const int* __restrict__ ei2, int E1, int E2)
{
    int e = blockIdx.x * 256 + threadIdx.x;
    if (e < E1) {
        int s = __ldg(ei1 + e);
        int d = __ldg(ei1 + E1 + e);
        int pos = atomicAdd(&g_cursor[d], 1);
        g_nbr[pos] = s;
    }
    int e2 = e - E1;
    if (e2 >= 0 && e2 < E2) {
        int s = __ldg(ei2 + e2);
        int d = __ldg(ei2 + E2 + e2);
        int pos = atomicAdd(&g_cursor[NMAX + d], 1);
        g_nbr[EMAX + pos] = s;
    }
}

// ---------------------------------------------------------------------------
// Gather-mean fp16 in / fp16 out, fp32 accumulate, 8-wide MLP
// ---------------------------------------------------------------------------
__device__ __forceinline__ void add_f16x4(float4& acc, uint2 p) {
    float2 a = __half22float2(*reinterpret_cast<__half2*>(&p.x));
    float2 b = __half22float2(*reinterpret_cast<__half2*>(&p.y));
    acc.x += a.x; acc.y += a.y; acc.z += b.x; acc.w += b.y;
}

__global__ void __launch_bounds__(256) gather_h16_kernel(
    const unsigned short* __restrict__ feath, int n, int csr)
{
    int v = (blockIdx.x * 256 + threadIdx.x) >> 5;
    int lane = threadIdx.x & 31;
    if (v >= n) return;
    int start = __ldg(g_off + csr * NMAX + v);
    int deg   = __ldg(g_deg + csr * NMAX + v);
    const int* nbr = g_nbr + csr * EMAX;
    const uint2* f = reinterpret_cast<const uint2*>(feath);
    float4 acc = make_float4(0.f, 0.f, 0.f, 0.f);
    int i = 0;
    for (; i + 8 <= deg; i += 8) {
        int s_[8];
#pragma unroll
        for (int u = 0; u < 8; u++) s_[u] = __ldg(nbr + start + i + u);
        uint2 p[8];
#pragma unroll
        for (int u = 0; u < 8; u++) p[u] = __ldg(f + (size_t)s_[u] * 32 + lane);
#pragma unroll
        for (int u = 0; u < 8; u++) add_f16x4(acc, p[u]);
    }
    for (; i + 4 <= deg; i += 4) {
        int s_[4];
#pragma unroll
        for (int u = 0; u < 4; u++) s_[u] = __ldg(nbr + start + i + u);
        uint2 p[4];
#pragma unroll
        for (int u = 0; u < 4; u++) p[u] = __ldg(f + (size_t)s_[u] * 32 + lane);
#pragma unroll
        for (int u = 0; u < 4; u++) add_f16x4(acc, p[u]);
    }
    for (; i < deg; i++) {
        int s0 = __ldg(nbr + start + i);
        uint2 p0 = __ldg(f + (size_t)s0 * 32 + lane);
        add_f16x4(acc, p0);
    }
    float inv = 1.0f / (float)max(deg, 1);
    reinterpret_cast<uint2*>(g_aggh)[(size_t)v * 32 + lane] =
        make_uint2(pack_h2(acc.x * inv, acc.y * inv),
                   pack_h2(acc.z * inv, acc.w * inv));
}

// ---------------------------------------------------------------------------
// HMMA SAGE layer: 128-row tile, 512 threads (16 warps = 8M x 2N, warp 16x64).
// Both W chunks staged up front; A1 register-prefetched during chunk-0 stage
// so the inter-chunk boundary is STS-only (no gmem stall).
// MODE 0: out -> g_h1h (fp16).  relu(agg@wl + xin@wr + b)
// MODE 1: layer-2 + fused head (fp16 2-product exact-W) -> d_out [n,40].
// ---------------------------------------------------------------------------
template <int MODE>
__global__ void __launch_bounds__(512) layer_mma_kernel(
    const unsigned short* __restrict__ xin_h, const float* __restrict__ bias,
    float* __restrict__ out, int n,
    const unsigned short* __restrict__ wth_base,
    const float* __restrict__ b_out)
{
    extern __shared__ unsigned short sm[];
    unsigned short* s_a  = sm;                       // 128 x APAD (fp16)
    unsigned short* s_w0 = sm + 128 * APAD;          // 128 x APAD (chunk-0 W)
    unsigned short* s_w1 = sm + 2 * 128 * APAD;      // 128 x APAD (chunk-1 W)

    int tid = threadIdx.x, wid = tid >> 5, lane = tid & 31;
    int r0 = blockIdx.x * 128;
    int mrow = (wid & 7) * 16;    // warp M origin (16 rows)
    int ncol = (wid >> 3) * 64;   // warp N origin (64 cols)
    int rq = lane >> 2;

    unsigned base_a  = (unsigned)__cvta_generic_to_shared(s_a);
    unsigned base_w0 = (unsigned)__cvta_generic_to_shared(s_w0);
    unsigned base_w1 = (unsigned)__cvta_generic_to_shared(s_w1);

    int arow = mrow + (lane & 7) + ((lane >> 3) & 1) * 8;
    int akk  = (lane >> 4) * 8;
    unsigned aOff = (unsigned)((arow * APAD + akk) * 2);

    int bn  = ncol + ((lane >> 4) & 1) * 8 + (lane & 7);
    int bkk = ((lane >> 3) & 1) * 8;
    unsigned bOff[4];
#pragma unroll
    for (int p = 0; p < 4; p++)
        bOff[p] = (unsigned)(((bn + p * 16) * APAD + bkk) * 2);

    float acc[8][4];
#pragma unroll
    for (int nt = 0; nt < 8; nt++)
#pragma unroll
        for (int q = 0; q < 4; q++) acc[nt][q] = 0.f;

    // ---- stage: A0 + W0 + W1 into smem; A1 into registers ----
    const uint2* srcA0 = reinterpret_cast<const uint2*>(g_aggh);
    const uint2* srcA1 = reinterpret_cast<const uint2*>(xin_h);
    const uint2* gw = reinterpret_cast<const uint2*>(wth_base);
    uint2 ra[8];
#pragma unroll
    for (int i = 0; i < 8; i++) {
        int j = tid + i * 512;          // 128 rows * 32 uint2
        int row = j >> 5, k4 = j & 31;
        int gr = r0 + row;
        if (gr >= n) gr = n - 1;
        size_t go = (size_t)gr * 32 + k4;
        *reinterpret_cast<uint2*>(s_a + row * APAD + k4 * 4) = __ldg(srcA0 + go);
        ra[i] = __ldg(srcA1 + go);       // A1 prefetch (regs)
        int nrow = row, kk = k4 * 4;
        *reinterpret_cast<uint2*>(s_w0 + nrow * APAD + kk) = __ldg(gw + j);
        *reinterpret_cast<uint2*>(s_w1 + nrow * APAD + kk) = __ldg(gw + 4096 + j);
    }
    __syncthreads();

    // ---- compute chunk 0 ----
#pragma unroll
    for (int s = 0; s < 8; s++) {
        unsigned off = (unsigned)(s * 32);
        unsigned a[4];
        LDSM4(a, base_a + aOff + off);
#pragma unroll
        for (int p = 0; p < 4; p++) {
            unsigned bh[4];
            LDSM4(bh, base_w0 + bOff[p] + off);
            mma16816h(acc[p * 2 + 0], a, bh + 0);
            mma16816h(acc[p * 2 + 1], a, bh + 2);
        }
    }
    __syncthreads();

    // ---- swap in A1 (registers -> smem, no gmem wait) ----
#pragma unroll
    for (int i = 0; i < 8; i++) {
        int j = tid + i * 512;
        int row = j >> 5, k4 = j & 31;
        *reinterpret_cast<uint2*>(s_a + row * APAD + k4 * 4) = ra[i];
    }
    __syncthreads();

    // ---- compute chunk 1 ----
#pragma unroll
    for (int s = 0; s < 8; s++) {
        unsigned off = (unsigned)(s * 32);
        unsigned a[4];
        LDSM4(a, base_a + aOff + off);
#pragma unroll
        for (int p = 0; p < 4; p++) {
            unsigned bh[4];
            LDSM4(bh, base_w1 + bOff[p] + off);
            mma16816h(acc[p * 2 + 0], a, bh + 0);
            mma16816h(acc[p * 2 + 1], a, bh + 2);
        }
    }

    if (MODE == 0) {
        // ---- epilogue: bias + relu -> g_h1h (fp16) ----
#pragma unroll
        for (int nt = 0; nt < 8; nt++) {
            int col = ncol + nt * 8 + (lane & 3) * 2;
            float bx = __ldg(bias + col), by = __ldg(bias + col + 1);
#pragma unroll
            for (int q2 = 0; q2 < 2; q2++) {
                int row = r0 + mrow + rq + q2 * 8;
                if (row < n) {
                    float vx = fmaxf(acc[nt][q2 * 2 + 0] + bx, 0.f);
                    float vy = fmaxf(acc[nt][q2 * 2 + 1] + by, 0.f);
                    *reinterpret_cast<unsigned*>(g_h1h + (size_t)row * 128 + col)
                        = pack_h2(vx, vy);
                }
            }
        }
        return;
    }

    // ================= MODE 1: fused head (fp16, 2-product exact-W) ========
    __syncthreads();   // everyone done reading main-phase smem

    unsigned short* s_hh = sm;                       // 128 x HPAD (fp16 cat-tile)
    unsigned short* s_oh = sm + 128 * HPAD;          // 40 x HPAD
    unsigned short* s_ol = s_oh + 40 * HPAD;

    // 1) store relu(h2)+bias fragments into cat-tile cols [128..256)
#pragma unroll
    for (int nt = 0; nt < 8; nt++) {
        int col = ncol + nt * 8 + (lane & 3) * 2;
        float bx = __ldg(bias + col), by = __ldg(bias + col + 1);
#pragma unroll
        for (int q2 = 0; q2 < 2; q2++) {
            int row = mrow + rq + q2 * 8;
            float vx = fmaxf(acc[nt][q2 * 2 + 0] + bx, 0.f);
            float vy = fmaxf(acc[nt][q2 * 2 + 1] + by, 0.f);
            *reinterpret_cast<unsigned*>(s_hh + row * HPAD + 128 + col)
                = pack_h2(vx, vy);
        }
    }

    // 2) copy h1 rows (fp16, from register prefetch source) into cols [0..128)
    {
        const uint2* h1s = reinterpret_cast<const uint2*>(xin_h);  // == g_h1h
#pragma unroll
        for (int i = 0; i < 8; i++) {
            int j = tid + i * 512;
            int row = j >> 5, k4 = j & 31;
            int gr = r0 + row;
            if (gr >= n) gr = n - 1;
            *reinterpret_cast<uint2*>(s_hh + row * HPAD + k4 * 4) =
                __ldg(h1s + (size_t)gr * 32 + k4);
        }
    }

    // 3) stage w_out images [40 x 256] fp16 hi/lo
    {
        const uint2* gh = reinterpret_cast<const uint2*>(g_woth);
        const uint2* gl = reinterpret_cast<const uint2*>(g_wotl);
#pragma unroll
        for (int i = 0; i < 5; i++) {
            int j = tid + i * 512;            // 40*64 = 2560
            if (j < 2560) {
                int nn = j >> 6, kk = (j & 63) * 4;
                int o = nn * HPAD + kk;
                *reinterpret_cast<uint2*>(s_oh + o) = __ldg(gh + j);
                *reinterpret_cast<uint2*>(s_ol + o) = __ldg(gl + j);
            }
        }
    }
    __syncthreads();

    // 4) head GEMM: M=128 (8 warps x 16 rows), N=40; warp group covers
    //    n-tiles {0,1,2} (grp 0) or {3,4} (grp 1)
    int ngrp = wid >> 3;
    int mrow2 = (wid & 7) * 16;
    int nnt = ngrp ? 2 : 3;
    int ntbase = ngrp ? 3 : 0;
    int kc_h = (lane & 3) * 2;

    float acc2[3][4];
#pragma unroll
    for (int t = 0; t < 3; t++)
#pragma unroll
        for (int q = 0; q < 4; q++) acc2[t][q] = 0.f;

#pragma unroll
    for (int s = 0; s < 16; s++) {
        int kc = s * 16 + kc_h;
        unsigned ah[4];
        ah[0] = *reinterpret_cast<unsigned*>(s_hh + (mrow2 + rq) * HPAD + kc);
        ah[1] = *reinterpret_cast<unsigned*>(s_hh + (mrow2 + rq + 8) * HPAD + kc);
        ah[2] = *reinterpret_cast<unsigned*>(s_hh + (mrow2 + rq) * HPAD + kc + 8);
        ah[3] = *reinterpret_cast<unsigned*>(s_hh + (mrow2 + rq + 8) * HPAD + kc + 8);
        for (int t = 0; t < nnt; t++) {
            int nn = (ntbase + t) * 8 + rq;
            unsigned bh[2], bl[2];
            bh[0] = *reinterpret_cast<unsigned*>(s_oh + nn * HPAD + kc);
            bh[1] = *reinterpret_cast<unsigned*>(s_oh + nn * HPAD + kc + 8);
            bl[0] = *reinterpret_cast<unsigned*>(s_ol + nn * HPAD + kc);
            bl[1] = *reinterpret_cast<unsigned*>(s_ol + nn * HPAD + kc + 8);
            mma16816h(acc2[t], ah, bh);
            mma16816h(acc2[t], ah, bl);
        }
    }

    // 5) write d_out
    for (int t = 0; t < nnt; t++) {
        int col = (ntbase + t) * 8 + (lane & 3) * 2;
        float bx = __ldg(b_out + col), by = __ldg(b_out + col + 1);
#pragma unroll
        for (int q2 = 0; q2 < 2; q2++) {
            int row = r0 + mrow2 + rq + q2 * 8;
            if (row < n) {
                float2 o = make_float2(acc2[t][q2 * 2 + 0] + bx,
                                       acc2[t][q2 * 2 + 1] + by);
                *reinterpret_cast<float2*>(out + (size_t)row * 40 + col) = o;
            }
        }
    }
}

// ---------------------------------------------------------------------------
extern "C" void kernel_launch(void* const* d_in, const int* in_sizes, int n_in,
                              void* d_out, int out_size)
{
    const float* x     = (const float*)d_in[0];
    const int*   ei1   = (const int*)d_in[1];
    const int*   ei2   = (const int*)d_in[2];
    const float* wl1   = (const float*)d_in[3];
    const float* wr1   = (const float*)d_in[4];
    const float* b1    = (const float*)d_in[5];
    const float* wl2   = (const float*)d_in[6];
    const float* wr2   = (const float*)d_in[7];
    const float* b2    = (const float*)d_in[8];
    const float* w_out = (const float*)d_in[9];
    const float* b_out = (const float*)d_in[10];

    int n  = in_sizes[0] / D;
    int E1 = in_sizes[1] / 2;
    int E2 = in_sizes[2] / 2;

    void *p_wth = nullptr, *p_xh = nullptr, *p_h1h = nullptr;
    cudaGetSymbolAddress(&p_wth, g_wth);
    cudaGetSymbolAddress(&p_xh, g_xh);
    cudaGetSymbolAddress(&p_h1h, g_h1h);
    const unsigned short* wth = (const unsigned short*)p_wth;
    const unsigned short* xh  = (const unsigned short*)p_xh;
    const unsigned short* h1h = (const unsigned short*)p_h1h;

    // max(main phase 3*128*APAD*2 = 104448, head phase 109824)
    const int LAYER_SMEM = 128 * HPAD * 2 + 2 * 40 * HPAD * 2;  // 109824 B
    cudaFuncSetAttribute(layer_mma_kernel<0>,
                         cudaFuncAttributeMaxDynamicSharedMemorySize, LAYER_SMEM);
    cudaFuncSetAttribute(layer_mma_kernel<1>,
                         cudaFuncAttributeMaxDynamicSharedMemorySize, LAYER_SMEM);

    int nb_scan = (n + 1023) / 1024;
    int layer_blocks = (n + 127) / 128;
    int gather_blocks = (n * 32 + 255) / 256;

    // ---- prep (zero degs + weight images + convert x) ----
    prep_kernel<<<2048, 256>>>(wl1, wr1, wl2, wr2, w_out, x, n);

    // ---- batched CSR build for both edge lists ----
    count_both_kernel<<<(E1 + E2 + 255) / 256, 256>>>(ei1, ei2, E1, E2);
    scan1_kernel<<<dim3(nb_scan, 2), 1024>>>(n);
    scan23_kernel<<<dim3((n + 255) / 256, 2), 256>>>(n, nb_scan);
    fill_both_kernel<<<(E1 + E2 + 255) / 256, 256>>>(ei1, ei2, E1, E2);

    // ---- layer 1 ----
    gather_h16_kernel<<<gather_blocks, 256>>>(xh, n, 0);
    layer_mma_kernel<0><<<layer_blocks, 512, LAYER_SMEM>>>(
        xh, b1, nullptr, n, wth, b_out);

    // ---- layer 2 + fused head ----
    gather_h16_kernel<<<gather_blocks, 256>>>(h1h, n, 1);
    layer_mma_kernel<1><<<layer_blocks, 512, LAYER_SMEM>>>(
        h1h, b2, (float*)d_out, n, wth + 32768, b_out);
}